// round 12
// baseline (speedup 1.0000x reference)
#include <cuda_runtime.h>
#include <cuda_bf16.h>
#include <cstdint>
#include <cstddef>

// ---------------------------------------------------------------------------
// Problem constants
// ---------------------------------------------------------------------------
#define Bsz    8192
#define Tlen   64
#define MAXL   64
#define Cvoc   128
#define NS     56                 // samples per block
#define TPB    448                // 14 warps = 7 pairs; pair owns 8 samples
#define NBLK   147                // one wave on 148 SMs
#define G      4                  // samples per warp (own)

#define WORDS_ELEMS (Bsz * MAXL * Cvoc)
#define MU_OFF      ((size_t)WORDS_ELEMS)
#define LV_OFF      (MU_OFF + (size_t)Bsz * 20)

// ---------------------------------------------------------------------------
// Device scratch (static __device__ arrays: allocation-free)
// ---------------------------------------------------------------------------
__device__ float g_encf[Cvoc * 152];          // bih_f + embed_enc[c] @ Wih_f.T
__device__ float g_dect[Cvoc * 152];          // silu(embed_dec[c]) @ Wih1[:, :50].T
__device__ float g_bh  [Cvoc * 52];           // backward-cell output per token (h0=0)

// ---------------------------------------------------------------------------
// Shared memory layout (floats). Total 54944 floats = 219,776 B
// ---------------------------------------------------------------------------
#define oW1 0                    // 160x52
#define oW2 8320                 // 160x52   (token buffer overlay during encoder)
#define oW3 16640                // 160x52
#define oWO 24960                // 128x52
#define oB1 31616                // 160
#define oB2 31776                // 160
#define oB3 31936                // 160
#define oGA 32096                // 56x152
#define oGB 40608                // 56x152
#define oH1 49120                // 56x52
#define oH2 52032                // 56x52
#define SMEM_FLOATS 54944
#define SMEM_BYTES  (SMEM_FLOATS * 4)

// ---------------------------------------------------------------------------
// f32x2 packed FMA helpers
// ---------------------------------------------------------------------------
__device__ __forceinline__ unsigned long long fma2(unsigned long long a,
                                                   unsigned long long b,
                                                   unsigned long long c) {
    unsigned long long d;
    asm("fma.rn.f32x2 %0, %1, %2, %3;" : "=l"(d) : "l"(a), "l"(b), "l"(c));
    return d;
}
__device__ __forceinline__ float2 u2f(unsigned long long v) {
    float2 f;
    asm("mov.b64 {%0, %1}, %2;" : "=f"(f.x), "=f"(f.y) : "l"(v));
    return f;
}
__device__ __forceinline__ unsigned long long packf2(float x, float y) {
    unsigned long long v;
    asm("mov.b64 %0, {%1, %2};" : "=l"(v) : "f"(x), "f"(y));
    return v;
}
// precise (precompute-only)
__device__ __forceinline__ float sigm(float x) { return 1.0f / (1.0f + expf(-x)); }
// fast hot-loop nonlinearities (validated R10: no argmax flips)
__device__ __forceinline__ float sigmf(float x) {
    return __fdividef(1.0f, 1.0f + __expf(-x));
}
__device__ __forceinline__ float tanhfast(float x) {
    return __fdividef(2.0f, 1.0f + __expf(-2.0f * x)) - 1.0f;
}
// named barrier for warp pair pr (ids 1..7; 0 reserved for __syncthreads)
__device__ __forceinline__ void barp(int pr) {
    asm volatile("bar.sync %0, %1;" :: "r"(pr + 1), "r"(64) : "memory");
}

// ---------------------------------------------------------------------------
// Pair-split matvec: this warp computes rows l+32*(IB+i), i<IC, for the pair's
// 8 samples. Hp = pair hidden base (stride 52); Gp = pair gate base (stride 152).
// Weight rows are read by exactly ONE warp of the pair -> weight LDS halves.
// ---------------------------------------------------------------------------
template<int IB, int IC>
__device__ __forceinline__ void matvec_pair(const float* __restrict__ W,
                                            const float* __restrict__ Hp,
                                            const float* __restrict__ Bv,
                                            float* __restrict__ Gp,
                                            int l) {
    unsigned long long acc[IC][8];
#pragma unroll
    for (int i = 0; i < IC; i++)
#pragma unroll
        for (int g = 0; g < 8; g++) acc[i][g] = 0ull;
#pragma unroll 1
    for (int j = 0; j < 13; j++) {
        ulonglong2 hq[8];
#pragma unroll
        for (int g = 0; g < 8; g++)
            hq[g] = *reinterpret_cast<const ulonglong2*>(Hp + g * 52 + j * 4);
#pragma unroll
        for (int i = 0; i < IC; i++) {
            ulonglong2 wv = *reinterpret_cast<const ulonglong2*>(W + (l + 32 * (IB + i)) * 52 + j * 4);
#pragma unroll
            for (int g = 0; g < 8; g++) {
                acc[i][g] = fma2(wv.x, hq[g].x, acc[i][g]);
                acc[i][g] = fma2(wv.y, hq[g].y, acc[i][g]);
            }
        }
    }
#pragma unroll
    for (int i = 0; i < IC; i++) {
        int row = l + 32 * (IB + i);
        if (row < 152) {
            float b = Bv[row];
#pragma unroll
            for (int g = 0; g < 8; g++) {
                float2 f = u2f(acc[i][g]);
                Gp[g * 152 + row] = f.x + f.y + b;
            }
        }
    }
}

__device__ __forceinline__ void mvp(const float* __restrict__ W,
                                    const float* __restrict__ Hp,
                                    const float* __restrict__ Bv,
                                    float* __restrict__ Gp,
                                    int l, int half) {
    if (half == 0) matvec_pair<0, 3>(W, Hp, Bv, Gp, l);
    else           matvec_pair<3, 2>(W, Hp, Bv, Gp, l);
}

// ---------------------------------------------------------------------------
// Precompute kernel: per-token tables. Grid = 128 (one per token), 160 thr.
// ---------------------------------------------------------------------------
__global__ void vae_pre(const float* __restrict__ embed_enc,
                        const float* __restrict__ Wih_f, const float* __restrict__ bih_f,
                        const float* __restrict__ Wih_b, const float* __restrict__ bih_b,
                        const float* __restrict__ bhh_b,
                        const float* __restrict__ embed_dec,
                        const float* __restrict__ Wih1) {
    __shared__ float ee[50];
    __shared__ float ed[50];
    int c = blockIdx.x;
    int t = threadIdx.x;
    if (t < 50) {
        ee[t] = embed_enc[c * 50 + t];
        float e = embed_dec[c * 50 + t];
        ed[t] = e / (1.0f + expf(-e));      // silu
    }
    __syncthreads();

    if (t < 152) {
        float a = 0.0f, d = 0.0f;
        if (t < 150) {
            a = bih_f[t];
            for (int j = 0; j < 50; j++) {
                a = fmaf(ee[j], Wih_f[t * 50 + j], a);
                d = fmaf(ed[j], Wih1[t * 70 + j], d);
            }
        }
        g_encf[c * 152 + t] = a;
        g_dect[c * 152 + t] = d;
    }
    if (t < 52) {
        float hv = 0.0f;
        if (t < 50) {
            float gr = bih_b[t], gz = bih_b[50 + t], gn = bih_b[100 + t];
            for (int j = 0; j < 50; j++) {
                float e = ee[j];
                gr = fmaf(e, Wih_b[t * 50 + j], gr);
                gz = fmaf(e, Wih_b[(50 + t) * 50 + j], gz);
                gn = fmaf(e, Wih_b[(100 + t) * 50 + j], gn);
            }
            float rr = sigm(gr + bhh_b[t]);
            float zz = sigm(gz + bhh_b[50 + t]);
            float nn = tanhf(gn + rr * bhh_b[100 + t]);
            hv = (1.0f - zz) * nn;          // h0 = 0 => h' = (1-z)*n
        }
        g_bh[c * 52 + t] = hv;
    }
}

// ---------------------------------------------------------------------------
// Main fused kernel
// ---------------------------------------------------------------------------
__global__ void __launch_bounds__(TPB, 1)
vae_main(const int* __restrict__ x,
         const float* __restrict__ Whh_f, const float* __restrict__ bhh_f,
         const float* __restrict__ Wh2p,  const float* __restrict__ bh2p,
         const float* __restrict__ Wz2h,  const float* __restrict__ bz2h,
         const float* __restrict__ Wih1,  const float* __restrict__ bih1,
         const float* __restrict__ Whh1,  const float* __restrict__ bhh1,
         const float* __restrict__ Wih2,  const float* __restrict__ bih2,
         const float* __restrict__ Whh2,  const float* __restrict__ bhh2,
         const float* __restrict__ Wh2o,  const float* __restrict__ bh2o,
         float* __restrict__ out) {
    extern __shared__ float sm[];
    const int tid  = threadIdx.x;
    const int wrp  = tid >> 5;          // 0..13
    const int l    = tid & 31;
    const int pr   = wrp >> 1;          // pair 0..6
    const int half = wrp & 1;
    const int pb   = pr * 8;            // pair sample base
    const int sb   = pb + half * 4;     // own sample base
    const int bgrp = blockIdx.x * NS + sb;

    float* W1 = sm + oW1;
    float* W2 = sm + oW2;
    float* W3 = sm + oW3;
    float* WO = sm + oWO;
    float* B1 = sm + oB1;
    float* B2 = sm + oB2;
    float* B3 = sm + oB3;
    // own views (4 samples)
    float* GA = sm + oGA + sb * 152;
    float* GB = sm + oGB + sb * 152;
    float* H1 = sm + oH1 + sb * 52;
    float* H2 = sm + oH2 + sb * 52;
    // pair views (8 samples)
    float* GAp = sm + oGA + pb * 152;
    float* GBp = sm + oGB + pb * 152;
    float* H1p = sm + oH1 + pb * 52;
    float* H2p = sm + oH2 + pb * 52;
    int*   TOK = (int*)(sm + oW2);      // encoder-phase overlay of W2

    // ---- encoder weights (padded 160x52), tokens, zero H ----
    for (int i = tid; i < 160 * 52; i += TPB) {
        int row = i / 52, j = i % 52;
        W1[i] = (row < 150 && j < 50) ? Whh_f[row * 50 + j] : 0.0f;
    }
    for (int i = tid; i < 160; i += TPB) B1[i] = (i < 150) ? bhh_f[i] : 0.0f;
    for (int i = tid; i < NS * Tlen; i += TPB) {
        int s = i / Tlen;
        int b = blockIdx.x * NS + s; if (b >= Bsz) b = Bsz - 1;
        TOK[i] = x[b * Tlen + (i % Tlen)];
    }
    for (int i = tid; i < NS * 52; i += TPB) { sm[oH1 + i] = 0.0f; sm[oH2 + i] = 0.0f; }
    __syncthreads();

    // ================= ENCODER: 64 forward GRU steps (pair-split matvec) =====
    for (int t = 0; t < Tlen; t++) {
        // prefetch token-table rows for OWN samples (hides L2 latency)
        float pv[2][3][G];
#pragma unroll
        for (int rep = 0; rep < 2; rep++) {
            int u = l + 32 * rep;
            if (u < 50) {
#pragma unroll
                for (int g = 0; g < G; g++) {
                    const float* T = g_encf + TOK[(sb + g) * Tlen + t] * 152;
                    pv[rep][0][g] = __ldg(T + u);
                    pv[rep][1][g] = __ldg(T + 50 + u);
                    pv[rep][2][g] = __ldg(T + 100 + u);
                }
            }
        }
        mvp(W1, H1p, B1, GBp, l, half);   // pair-split: each warp half the rows
        barp(pr);
#pragma unroll
        for (int rep = 0; rep < 2; rep++) {
            int u = l + 32 * rep;
            if (u < 50) {
                float b0[G], b1[G], b2[G], hold[G];
#pragma unroll
                for (int g = 0; g < G; g++) {
                    const float* gb = GB + g * 152;
                    b0[g] = gb[u]; b1[g] = gb[50 + u]; b2[g] = gb[100 + u];
                    hold[g] = H1[g * 52 + u];
                }
#pragma unroll
                for (int g = 0; g < G; g++) {
                    float r = sigmf(pv[rep][0][g] + b0[g]);
                    float z = sigmf(pv[rep][1][g] + b1[g]);
                    float n = tanhfast(pv[rep][2][g] + r * b2[g]);
                    H1[g * 52 + u] = (1.0f - z) * n + z * hold[g];
                }
            }
        }
        barp(pr);                          // H1 pair-visible for next matvec
    }

    // ---- backward cell add (own samples, pure table) ----
#pragma unroll
    for (int rep = 0; rep < 2; rep++) {
        int u = l + 32 * rep;
        if (u < 50) {
#pragma unroll
            for (int g = 0; g < G; g++) {
                int cl = TOK[(sb + g) * Tlen + Tlen - 1];
                H1[g * 52 + u] += __ldg(g_bh + cl * 52 + u);
            }
        }
    }
    __syncwarp();

    // ---- p = h_enc@Wh2p.T + bh2p ; z=mu -> GB[0:20]; mu/logvar out ----
#pragma unroll
    for (int k = 0; k < 2; k++) {
        int row = l + 32 * k;
        if (row < 40) {
            float accv[G];
#pragma unroll
            for (int g = 0; g < G; g++) accv[g] = __ldg(bh2p + row);
            for (int j = 0; j < 50; j++) {
                float wv = __ldg(Wh2p + row * 50 + j);
#pragma unroll
                for (int g = 0; g < G; g++) accv[g] = fmaf(wv, H1[g * 52 + j], accv[g]);
            }
            for (int g = 0; g < G; g++) {
                int b = bgrp + g;
                if (row < 20) {
                    GB[g * 152 + row] = accv[g];         // z = mu
                    if (b < Bsz) out[MU_OFF + (size_t)b * 20 + row] = accv[g];
                } else {
                    if (b < Bsz) out[LV_OFF + (size_t)b * 20 + (row - 20)] = accv[g];
                }
            }
        }
    }
    __syncwarp();

    // ---- h_init (h1=h2) from z ----
#pragma unroll
    for (int k = 0; k < 2; k++) {
        int row = l + 32 * k;
        if (row < 50) {
            float accv[G];
#pragma unroll
            for (int g = 0; g < G; g++) accv[g] = __ldg(bz2h + row);
            for (int j = 0; j < 20; j++) {
                float wv = __ldg(Wz2h + row * 20 + j);
#pragma unroll
                for (int g = 0; g < G; g++) accv[g] = fmaf(wv, GB[g * 152 + j], accv[g]);
            }
            for (int g = 0; g < G; g++) { H1[g * 52 + row] = accv[g]; H2[g * 52 + row] = accv[g]; }
        }
    }

    // ---- giz = bih1 + z @ Wih1[:,50:70].T  -> staged in GA (own) ----
#pragma unroll
    for (int k = 0; k < 5; k++) {
        int row = l + 32 * k;
        if (row < 150) {
            float accv[G];
#pragma unroll
            for (int g = 0; g < G; g++) accv[g] = __ldg(bih1 + row);
            for (int j = 0; j < 20; j++) {
                float wv = __ldg(Wih1 + row * 70 + 50 + j);
#pragma unroll
                for (int g = 0; g < G; g++) accv[g] = fmaf(wv, GB[g * 152 + j], accv[g]);
            }
            for (int g = 0; g < G; g++) GA[g * 152 + row] = accv[g];
        }
    }

    // ---- outz = bh2o + z @ Wh2o[:,50:70].T -> HELD IN REGISTERS (oz) ----
    float oz[4][G];
#pragma unroll
    for (int k = 0; k < 4; k++) {
        int row = l + 32 * k;   // < 128 always
#pragma unroll
        for (int g = 0; g < G; g++) oz[k][g] = __ldg(bh2o + row);
        for (int j = 0; j < 20; j++) {
            float wv = __ldg(Wh2o + row * 70 + 50 + j);
#pragma unroll
            for (int g = 0; g < G; g++) oz[k][g] = fmaf(wv, GB[g * 152 + j], oz[k][g]);
        }
    }
    __syncwarp();

    // ---- pull this lane's 6 giz values per own sample into registers ----
    float gz0[3][G], gz1[3][G];
#pragma unroll
    for (int g = 0; g < G; g++) {
        const float* gp = GA + g * 152;
        gz0[0][g] = gp[l];       gz0[1][g] = gp[50 + l];  gz0[2][g] = gp[100 + l];
        if (l < 18) {
            gz1[0][g] = gp[32 + l]; gz1[1][g] = gp[82 + l]; gz1[2][g] = gp[132 + l];
        } else {
            gz1[0][g] = 0.0f; gz1[1][g] = 0.0f; gz1[2][g] = 0.0f;
        }
    }
    __syncthreads();

    // ---- swap smem to decoder weights (W2 overwrites token buffer) ----
    for (int i = tid; i < 160 * 52; i += TPB) {
        int row = i / 52, j = i % 52;
        bool ok = (row < 150 && j < 50);
        W1[i] = ok ? Whh1[row * 50 + j] : 0.0f;
        W2[i] = ok ? Wih2[row * 50 + j] : 0.0f;
        W3[i] = ok ? Whh2[row * 50 + j] : 0.0f;
    }
    for (int i = tid; i < 128 * 52; i += TPB) {
        int row = i / 52, j = i % 52;
        WO[i] = (j < 50) ? Wh2o[row * 70 + j] : 0.0f;
    }
    for (int i = tid; i < 160; i += TPB) {
        bool ok = (i < 150);
        B1[i] = ok ? bhh1[i] : 0.0f;
        B2[i] = ok ? bih2[i] : 0.0f;
        B3[i] = ok ? bhh2[i] : 0.0f;
    }
    __syncthreads();

    // ================= DECODER: 64 autoregressive steps ======================
    int ct[G];
#pragma unroll
    for (int g = 0; g < G; g++) ct[g] = 1;   // SOS

    // prologue: MV1 (pair-split) for step 0 -> GBp
    mvp(W1, H1p, B1, GBp, l, half);

    for (int t = 0; t < MAXL; t++) {
        // a) prefetch token-table rows for own gates1 (covered by MV3)
        float pd[2][3][G];
#pragma unroll
        for (int rep = 0; rep < 2; rep++) {
            int u = l + 32 * rep;
            if (u < 50) {
#pragma unroll
                for (int g = 0; g < G; g++) {
                    const float* T = g_dect + ct[g] * 152;
                    pd[rep][0][g] = __ldg(T + u);
                    pd[rep][1][g] = __ldg(T + 50 + u);
                    pd[rep][2][g] = __ldg(T + 100 + u);
                }
            }
        }

        // b) MV3: gh2 = h2 @ Whh2.T + bhh2 (pair-split) -> GAp
        mvp(W3, H2p, B3, GAp, l, half);
        barp(pr);   // c: GA complete; GB (MV1 prev) pair-visible

        // d) gates1 own: H1 update (GB = MV1 result, pd, gz)
#pragma unroll
        for (int rep = 0; rep < 2; rep++) {
            int u = l + 32 * rep;
            if (u < 50) {
                float b0[G], b1[G], b2[G], hold[G];
#pragma unroll
                for (int g = 0; g < G; g++) {
                    const float* gb = GB + g * 152;
                    b0[g] = gb[u]; b1[g] = gb[50 + u]; b2[g] = gb[100 + u];
                    hold[g] = H1[g * 52 + u];
                }
#pragma unroll
                for (int g = 0; g < G; g++) {
                    float a0 = pd[rep][0][g] + (rep ? gz1[0][g] : gz0[0][g]) + b0[g];
                    float a1 = pd[rep][1][g] + (rep ? gz1[1][g] : gz0[1][g]) + b1[g];
                    float a2 = pd[rep][2][g] + (rep ? gz1[2][g] : gz0[2][g]);
                    float r = sigmf(a0);
                    float z = sigmf(a1);
                    float n = tanhfast(a2 + r * b2[g]);
                    H1[g * 52 + u] = (1.0f - z) * n + z * hold[g];
                }
            }
        }
        barp(pr);   // e: H1 pair-visible

        // f) MV2: gi2 = h1_new @ Wih2.T + bih2 (pair-split) -> GBp
        mvp(W2, H1p, B2, GBp, l, half);
        barp(pr);   // g: GB complete

        // h) gates2 own: H2 update from GB(gi2) + GA(gh2)
#pragma unroll
        for (int rep = 0; rep < 2; rep++) {
            int u = l + 32 * rep;
            if (u < 50) {
                float i0[G], i1[G], i2v[G], h0[G], h1v[G], h2v[G], hold[G];
#pragma unroll
                for (int g = 0; g < G; g++) {
                    const float* gi = GB + g * 152;
                    const float* gh = GA + g * 152;
                    i0[g] = gi[u]; i1[g] = gi[50 + u]; i2v[g] = gi[100 + u];
                    h0[g] = gh[u]; h1v[g] = gh[50 + u]; h2v[g] = gh[100 + u];
                    hold[g] = H2[g * 52 + u];
                }
#pragma unroll
                for (int g = 0; g < G; g++) {
                    float r = sigmf(i0[g] + h0[g]);
                    float z = sigmf(i1[g] + h1v[g]);
                    float n = tanhfast(i2v[g] + r * h2v[g]);
                    H2[g * 52 + u] = (1.0f - z) * n + z * hold[g];
                }
            }
        }
        barp(pr);   // i: H2 pair-visible; GB reads done (MV1next may overwrite)

        // j) output projection own: vals = WO @ h2 + oz (reads own H2 only)
        float vals[4][G];
        {
            unsigned long long aco[4][G];
#pragma unroll
            for (int i = 0; i < 4; i++)
#pragma unroll
                for (int g = 0; g < G; g++) aco[i][g] = packf2(oz[i][g], 0.0f);
#pragma unroll 1
            for (int j = 0; j < 13; j++) {
                ulonglong2 hq2[G];
#pragma unroll
                for (int g = 0; g < G; g++)
                    hq2[g] = *reinterpret_cast<const ulonglong2*>(H2 + g * 52 + j * 4);
#pragma unroll
                for (int i = 0; i < 4; i++) {
                    ulonglong2 wv = *reinterpret_cast<const ulonglong2*>(WO + (l + 32 * i) * 52 + j * 4);
#pragma unroll
                    for (int g = 0; g < G; g++) {
                        aco[i][g] = fma2(wv.x, hq2[g].x, aco[i][g]);
                        aco[i][g] = fma2(wv.y, hq2[g].y, aco[i][g]);
                    }
                }
            }
#pragma unroll
            for (int i = 0; i < 4; i++)
#pragma unroll
                for (int g = 0; g < G; g++) {
                    float2 f = u2f(aco[i][g]);
                    vals[i][g] = f.x + f.y;
                }
        }

        // k) MV1 for NEXT step (pair-split; H1 final since bar e) -> GBp
        mvp(W1, H1p, B1, GBp, l, half);

        // l) merged argmax + direct exp-sum + store (own samples)
        float m[G]; int mi[G]; float ss[G];
#pragma unroll
        for (int g = 0; g < G; g++) {
            m[g] = vals[0][g]; mi[g] = l;
            ss[g] = __expf(vals[0][g]);
#pragma unroll
            for (int i = 1; i < 4; i++) {
                ss[g] += __expf(vals[i][g]);
                if (vals[i][g] > m[g]) { m[g] = vals[i][g]; mi[g] = l + 32 * i; }
            }
        }
#pragma unroll
        for (int off = 16; off >= 1; off >>= 1) {
#pragma unroll
            for (int g = 0; g < G; g++) {
                float m2 = __shfl_xor_sync(0xffffffffu, m[g], off);
                int   i2 = __shfl_xor_sync(0xffffffffu, mi[g], off);
                float s2 = __shfl_xor_sync(0xffffffffu, ss[g], off);
                ss[g] += s2;
                if (m2 > m[g] || (m2 == m[g] && i2 < mi[g])) { m[g] = m2; mi[g] = i2; }
            }
        }
#pragma unroll
        for (int g = 0; g < G; g++) {
            float lse = __logf(ss[g]);
            ct[g] = mi[g];
            int b = bgrp + g;
            if (b < Bsz) {
                float* wp = out + (size_t)b * (MAXL * Cvoc) + (size_t)t * Cvoc;
#pragma unroll
                for (int i = 0; i < 4; i++) wp[l + 32 * i] = vals[i][g] - lse;
            }
        }
        // loop top's barp(c) orders MV1next(GB) & gates2-era H2 across the pair
    }
}

// ---------------------------------------------------------------------------
// Launch
// ---------------------------------------------------------------------------
extern "C" void kernel_launch(void* const* d_in, const int* in_sizes, int n_in,
                              void* d_out, int out_size) {
    const int*   x         = (const int*)  d_in[0];
    const float* embed_enc = (const float*)d_in[1];
    const float* Wih_f     = (const float*)d_in[2];
    const float* Whh_f     = (const float*)d_in[3];
    const float* bih_f     = (const float*)d_in[4];
    const float* bhh_f     = (const float*)d_in[5];
    const float* Wih_b     = (const float*)d_in[6];
    const float* Whh_b     = (const float*)d_in[7];  (void)Whh_b;  // h0=0: unused
    const float* bih_b     = (const float*)d_in[8];
    const float* bhh_b     = (const float*)d_in[9];
    const float* Wh2p      = (const float*)d_in[10];
    const float* bh2p      = (const float*)d_in[11];
    const float* embed_dec = (const float*)d_in[12];
    const float* Wz2h      = (const float*)d_in[13];
    const float* bz2h      = (const float*)d_in[14];
    const float* Wih1      = (const float*)d_in[15];
    const float* Whh1      = (const float*)d_in[16];
    const float* bih1      = (const float*)d_in[17];
    const float* bhh1      = (const float*)d_in[18];
    const float* Wih2      = (const float*)d_in[19];
    const float* Whh2      = (const float*)d_in[20];
    const float* bih2      = (const float*)d_in[21];
    const float* bhh2      = (const float*)d_in[22];
    const float* Wh2o      = (const float*)d_in[23];
    const float* bh2o      = (const float*)d_in[24];
    float* out = (float*)d_out;

    cudaFuncSetAttribute(vae_main, cudaFuncAttributeMaxDynamicSharedMemorySize, SMEM_BYTES);

    vae_pre<<<Cvoc, 160>>>(embed_enc, Wih_f, bih_f, Wih_b, bih_b, bhh_b, embed_dec, Wih1);
    vae_main<<<NBLK, TPB, SMEM_BYTES>>>(x,
                                        Whh_f, bhh_f, Wh2p, bh2p, Wz2h, bz2h,
                                        Wih1, bih1, Whh1, bhh1, Wih2, bih2,
                                        Whh2, bhh2, Wh2o, bh2o, out);
}

// round 13
// speedup vs baseline: 1.1515x; 1.1515x over previous
#include <cuda_runtime.h>
#include <cuda_bf16.h>
#include <cstdint>
#include <cstddef>

// ---------------------------------------------------------------------------
// Problem constants
// ---------------------------------------------------------------------------
#define Bsz    8192
#define Tlen   64
#define MAXL   64
#define Cvoc   128
#define NS     56                 // samples per block
#define TPB    448                // 14 warps; each warp owns 4 samples
#define NBLK   147                // one wave on 148 SMs
#define G      4                  // samples per warp

#define WORDS_ELEMS (Bsz * MAXL * Cvoc)
#define MU_OFF      ((size_t)WORDS_ELEMS)
#define LV_OFF      (MU_OFF + (size_t)Bsz * 20)

// ---------------------------------------------------------------------------
// Device scratch (static __device__ arrays: allocation-free)
// ---------------------------------------------------------------------------
__device__ float g_encf[Cvoc * 152];          // bih_f + embed_enc[c] @ Wih_f.T
__device__ float g_dect[Cvoc * 152];          // silu(embed_dec[c]) @ Wih1[:, :50].T
__device__ float g_bh  [Cvoc * 52];           // backward-cell output per token (h0=0)

// ---------------------------------------------------------------------------
// Shared memory layout (floats). Total 54944 floats = 219,776 B
// ---------------------------------------------------------------------------
#define oW1 0                    // 160x52
#define oW2 8320                 // 160x52   (token buffer overlay during encoder)
#define oW3 16640                // 160x52
#define oWO 24960                // 128x52
#define oB1 31616                // 160
#define oB2 31776                // 160
#define oB3 31936                // 160
#define oGA 32096                // 56x152
#define oGB 40608                // 56x152
#define oH1 49120                // 56x52
#define oH2 52032                // 56x52
#define SMEM_FLOATS 54944
#define SMEM_BYTES  (SMEM_FLOATS * 4)

// ---------------------------------------------------------------------------
// f32x2 packed FMA helpers
// ---------------------------------------------------------------------------
__device__ __forceinline__ unsigned long long fma2(unsigned long long a,
                                                   unsigned long long b,
                                                   unsigned long long c) {
    unsigned long long d;
    asm("fma.rn.f32x2 %0, %1, %2, %3;" : "=l"(d) : "l"(a), "l"(b), "l"(c));
    return d;
}
__device__ __forceinline__ float2 u2f(unsigned long long v) {
    float2 f;
    asm("mov.b64 {%0, %1}, %2;" : "=f"(f.x), "=f"(f.y) : "l"(v));
    return f;
}
__device__ __forceinline__ unsigned long long packf2(float x, float y) {
    unsigned long long v;
    asm("mov.b64 %0, {%1, %2};" : "=l"(v) : "f"(x), "f"(y));
    return v;
}
// precise (precompute-only)
__device__ __forceinline__ float sigm(float x) { return 1.0f / (1.0f + expf(-x)); }
// fast hot-loop nonlinearities (validated R10: no argmax flips)
__device__ __forceinline__ float sigmf(float x) {
    return __fdividef(1.0f, 1.0f + __expf(-x));
}
__device__ __forceinline__ float tanhfast(float x) {
    return __fdividef(2.0f, 1.0f + __expf(-2.0f * x)) - 1.0f;
}

// ---------------------------------------------------------------------------
// Warp-group matvec: rows l+32i (i<R, weights padded to >=32R x 52), G samples.
// j-loop unroll 2: doubles in-flight LDS to cover the 29-cyc smem latency.
// ---------------------------------------------------------------------------
template<int R>
__device__ __forceinline__ void matvec_g(const float* __restrict__ W,
                                         const float* __restrict__ Hs,
                                         const float* __restrict__ Bv,
                                         float* __restrict__ Gout,
                                         int l) {
    unsigned long long acc[R][G];
#pragma unroll
    for (int i = 0; i < R; i++)
#pragma unroll
        for (int g = 0; g < G; g++) acc[i][g] = 0ull;
#pragma unroll 2
    for (int j = 0; j < 13; j++) {
        ulonglong2 hq[G];
#pragma unroll
        for (int g = 0; g < G; g++)
            hq[g] = *reinterpret_cast<const ulonglong2*>(Hs + g * 52 + j * 4);
#pragma unroll
        for (int i = 0; i < R; i++) {
            ulonglong2 wv = *reinterpret_cast<const ulonglong2*>(W + (l + 32 * i) * 52 + j * 4);
#pragma unroll
            for (int g = 0; g < G; g++) {
                acc[i][g] = fma2(wv.x, hq[g].x, acc[i][g]);
                acc[i][g] = fma2(wv.y, hq[g].y, acc[i][g]);
            }
        }
    }
#pragma unroll
    for (int i = 0; i < R; i++) {
        int row = l + 32 * i;
        if (row < 152) {
            float b = Bv[row];
#pragma unroll
            for (int g = 0; g < G; g++) {
                float2 f = u2f(acc[i][g]);
                Gout[g * 152 + row] = f.x + f.y + b;
            }
        }
    }
}

// ---------------------------------------------------------------------------
// Precompute kernel: per-token tables. Grid = 128 (one per token), 160 thr.
// ---------------------------------------------------------------------------
__global__ void vae_pre(const float* __restrict__ embed_enc,
                        const float* __restrict__ Wih_f, const float* __restrict__ bih_f,
                        const float* __restrict__ Wih_b, const float* __restrict__ bih_b,
                        const float* __restrict__ bhh_b,
                        const float* __restrict__ embed_dec,
                        const float* __restrict__ Wih1) {
    __shared__ float ee[50];
    __shared__ float ed[50];
    int c = blockIdx.x;
    int t = threadIdx.x;
    if (t < 50) {
        ee[t] = embed_enc[c * 50 + t];
        float e = embed_dec[c * 50 + t];
        ed[t] = e / (1.0f + expf(-e));      // silu
    }
    __syncthreads();

    if (t < 152) {
        float a = 0.0f, d = 0.0f;
        if (t < 150) {
            a = bih_f[t];
            for (int j = 0; j < 50; j++) {
                a = fmaf(ee[j], Wih_f[t * 50 + j], a);
                d = fmaf(ed[j], Wih1[t * 70 + j], d);
            }
        }
        g_encf[c * 152 + t] = a;
        g_dect[c * 152 + t] = d;
    }
    if (t < 52) {
        float hv = 0.0f;
        if (t < 50) {
            float gr = bih_b[t], gz = bih_b[50 + t], gn = bih_b[100 + t];
            for (int j = 0; j < 50; j++) {
                float e = ee[j];
                gr = fmaf(e, Wih_b[t * 50 + j], gr);
                gz = fmaf(e, Wih_b[(50 + t) * 50 + j], gz);
                gn = fmaf(e, Wih_b[(100 + t) * 50 + j], gn);
            }
            float rr = sigm(gr + bhh_b[t]);
            float zz = sigm(gz + bhh_b[50 + t]);
            float nn = tanhf(gn + rr * bhh_b[100 + t]);
            hv = (1.0f - zz) * nn;          // h0 = 0 => h' = (1-z)*n
        }
        g_bh[c * 52 + t] = hv;
    }
}

// ---------------------------------------------------------------------------
// Main fused kernel
// ---------------------------------------------------------------------------
__global__ void __launch_bounds__(TPB, 1)
vae_main(const int* __restrict__ x,
         const float* __restrict__ Whh_f, const float* __restrict__ bhh_f,
         const float* __restrict__ Wh2p,  const float* __restrict__ bh2p,
         const float* __restrict__ Wz2h,  const float* __restrict__ bz2h,
         const float* __restrict__ Wih1,  const float* __restrict__ bih1,
         const float* __restrict__ Whh1,  const float* __restrict__ bhh1,
         const float* __restrict__ Wih2,  const float* __restrict__ bih2,
         const float* __restrict__ Whh2,  const float* __restrict__ bhh2,
         const float* __restrict__ Wh2o,  const float* __restrict__ bh2o,
         float* __restrict__ out) {
    extern __shared__ float sm[];
    const int tid  = threadIdx.x;
    const int wrp  = tid >> 5;          // 0..13
    const int l    = tid & 31;
    const int sb   = wrp * G;           // warp's sample base within block
    const int bgrp = blockIdx.x * NS + sb;

    float* W1 = sm + oW1;
    float* W2 = sm + oW2;
    float* W3 = sm + oW3;
    float* WO = sm + oWO;
    float* B1 = sm + oB1;
    float* B2 = sm + oB2;
    float* B3 = sm + oB3;
    float* GA = sm + oGA + sb * 152;
    float* GB = sm + oGB + sb * 152;
    float* H1 = sm + oH1 + sb * 52;
    float* H2 = sm + oH2 + sb * 52;
    int*   TOK = (int*)(sm + oW2);      // encoder-phase overlay of W2

    // ---- encoder weights (padded 160x52), tokens, zero H ----
    for (int i = tid; i < 160 * 52; i += TPB) {
        int row = i / 52, j = i % 52;
        W1[i] = (row < 150 && j < 50) ? Whh_f[row * 50 + j] : 0.0f;
    }
    for (int i = tid; i < 160; i += TPB) B1[i] = (i < 150) ? bhh_f[i] : 0.0f;
    for (int i = tid; i < NS * Tlen; i += TPB) {
        int s = i / Tlen;
        int b = blockIdx.x * NS + s; if (b >= Bsz) b = Bsz - 1;
        TOK[i] = x[b * Tlen + (i % Tlen)];
    }
    for (int i = tid; i < NS * 52; i += TPB) { sm[oH1 + i] = 0.0f; sm[oH2 + i] = 0.0f; }
    __syncthreads();

    // ================= ENCODER: 64 forward GRU steps =================
    for (int t = 0; t < Tlen; t++) {
        // prefetch token-table rows BEFORE matvec (hides L2 latency)
        float pv[2][3][G];
#pragma unroll
        for (int rep = 0; rep < 2; rep++) {
            int u = l + 32 * rep;
            if (u < 50) {
#pragma unroll
                for (int g = 0; g < G; g++) {
                    const float* T = g_encf + TOK[(sb + g) * Tlen + t] * 152;
                    pv[rep][0][g] = __ldg(T + u);
                    pv[rep][1][g] = __ldg(T + 50 + u);
                    pv[rep][2][g] = __ldg(T + 100 + u);
                }
            }
        }
        matvec_g<5>(W1, H1, B1, GB, l);
        __syncwarp();
#pragma unroll
        for (int rep = 0; rep < 2; rep++) {
            int u = l + 32 * rep;
            if (u < 50) {
                float b0[G], b1[G], b2[G], hold[G];
#pragma unroll
                for (int g = 0; g < G; g++) {
                    const float* gb = GB + g * 152;
                    b0[g] = gb[u]; b1[g] = gb[50 + u]; b2[g] = gb[100 + u];
                    hold[g] = H1[g * 52 + u];
                }
#pragma unroll
                for (int g = 0; g < G; g++) {
                    float r = sigmf(pv[rep][0][g] + b0[g]);
                    float z = sigmf(pv[rep][1][g] + b1[g]);
                    float n = tanhfast(pv[rep][2][g] + r * b2[g]);
                    H1[g * 52 + u] = (1.0f - z) * n + z * hold[g];
                }
            }
        }
        __syncwarp();
    }

    // ---- backward cell add (pure table) ----
#pragma unroll
    for (int rep = 0; rep < 2; rep++) {
        int u = l + 32 * rep;
        if (u < 50) {
#pragma unroll
            for (int g = 0; g < G; g++) {
                int cl = TOK[(sb + g) * Tlen + Tlen - 1];
                H1[g * 52 + u] += __ldg(g_bh + cl * 52 + u);
            }
        }
    }
    __syncwarp();

    // ---- p = h_enc@Wh2p.T + bh2p ; z=mu -> GB[0:20]; mu/logvar out ----
#pragma unroll
    for (int k = 0; k < 2; k++) {
        int row = l + 32 * k;
        if (row < 40) {
            float accv[G];
#pragma unroll
            for (int g = 0; g < G; g++) accv[g] = __ldg(bh2p + row);
            for (int j = 0; j < 50; j++) {
                float wv = __ldg(Wh2p + row * 50 + j);
#pragma unroll
                for (int g = 0; g < G; g++) accv[g] = fmaf(wv, H1[g * 52 + j], accv[g]);
            }
            for (int g = 0; g < G; g++) {
                int b = bgrp + g;
                if (row < 20) {
                    GB[g * 152 + row] = accv[g];         // z = mu
                    if (b < Bsz) out[MU_OFF + (size_t)b * 20 + row] = accv[g];
                } else {
                    if (b < Bsz) out[LV_OFF + (size_t)b * 20 + (row - 20)] = accv[g];
                }
            }
        }
    }
    __syncwarp();

    // ---- h_init (h1=h2) from z ----
#pragma unroll
    for (int k = 0; k < 2; k++) {
        int row = l + 32 * k;
        if (row < 50) {
            float accv[G];
#pragma unroll
            for (int g = 0; g < G; g++) accv[g] = __ldg(bz2h + row);
            for (int j = 0; j < 20; j++) {
                float wv = __ldg(Wz2h + row * 20 + j);
#pragma unroll
                for (int g = 0; g < G; g++) accv[g] = fmaf(wv, GB[g * 152 + j], accv[g]);
            }
            for (int g = 0; g < G; g++) { H1[g * 52 + row] = accv[g]; H2[g * 52 + row] = accv[g]; }
        }
    }

    // ---- giz = bih1 + z @ Wih1[:,50:70].T  -> staged in GA (smem) ----
#pragma unroll
    for (int k = 0; k < 5; k++) {
        int row = l + 32 * k;
        if (row < 150) {
            float accv[G];
#pragma unroll
            for (int g = 0; g < G; g++) accv[g] = __ldg(bih1 + row);
            for (int j = 0; j < 20; j++) {
                float wv = __ldg(Wih1 + row * 70 + 50 + j);
#pragma unroll
                for (int g = 0; g < G; g++) accv[g] = fmaf(wv, GB[g * 152 + j], accv[g]);
            }
            for (int g = 0; g < G; g++) GA[g * 152 + row] = accv[g];
        }
    }

    // ---- outz = bh2o + z @ Wh2o[:,50:70].T -> HELD IN REGISTERS (oz) ----
    float oz[4][G];
#pragma unroll
    for (int k = 0; k < 4; k++) {
        int row = l + 32 * k;   // < 128 always
#pragma unroll
        for (int g = 0; g < G; g++) oz[k][g] = __ldg(bh2o + row);
        for (int j = 0; j < 20; j++) {
            float wv = __ldg(Wh2o + row * 70 + 50 + j);
#pragma unroll
            for (int g = 0; g < G; g++) oz[k][g] = fmaf(wv, GB[g * 152 + j], oz[k][g]);
        }
    }
    __syncwarp();

    // ---- pull this lane's 6 giz values per sample into registers ----
    float gz0[3][G], gz1[3][G];
#pragma unroll
    for (int g = 0; g < G; g++) {
        const float* gp = GA + g * 152;
        gz0[0][g] = gp[l];       gz0[1][g] = gp[50 + l];  gz0[2][g] = gp[100 + l];
        if (l < 18) {
            gz1[0][g] = gp[32 + l]; gz1[1][g] = gp[82 + l]; gz1[2][g] = gp[132 + l];
        } else {
            gz1[0][g] = 0.0f; gz1[1][g] = 0.0f; gz1[2][g] = 0.0f;
        }
    }
    __syncthreads();

    // ---- swap smem to decoder weights (W2 overwrites token buffer) ----
    for (int i = tid; i < 160 * 52; i += TPB) {
        int row = i / 52, j = i % 52;
        bool ok = (row < 150 && j < 50);
        W1[i] = ok ? Whh1[row * 50 + j] : 0.0f;
        W2[i] = ok ? Wih2[row * 50 + j] : 0.0f;
        W3[i] = ok ? Whh2[row * 50 + j] : 0.0f;
    }
    for (int i = tid; i < 128 * 52; i += TPB) {
        int row = i / 52, j = i % 52;
        WO[i] = (j < 50) ? Wh2o[row * 70 + j] : 0.0f;
    }
    for (int i = tid; i < 160; i += TPB) {
        bool ok = (i < 150);
        B1[i] = ok ? bhh1[i] : 0.0f;
        B2[i] = ok ? bih2[i] : 0.0f;
        B3[i] = ok ? bhh2[i] : 0.0f;
    }
    __syncthreads();

    // ================= DECODER: 64 autoregressive steps (software-pipelined) ==
    int ct[G];
#pragma unroll
    for (int g = 0; g < G; g++) ct[g] = 1;   // SOS

    // prologue: MV1 for step 0
    matvec_g<5>(W1, H1, B1, GB, l);
    __syncwarp();

    for (int t = 0; t < MAXL; t++) {
        // -- prefetch token-table rows for gates1 (covered by MV3) --
        float pd[2][3][G];
#pragma unroll
        for (int rep = 0; rep < 2; rep++) {
            int u = l + 32 * rep;
            if (u < 50) {
#pragma unroll
                for (int g = 0; g < G; g++) {
                    const float* T = g_dect + ct[g] * 152;
                    pd[rep][0][g] = __ldg(T + u);
                    pd[rep][1][g] = __ldg(T + 50 + u);
                    pd[rep][2][g] = __ldg(T + 100 + u);
                }
            }
        }

        // -- MV3: gh2 = h2 @ Whh2.T + bhh2  (independent of gates1) --
        matvec_g<5>(W3, H2, B3, GA, l);
        __syncwarp();

        // -- gates1: h1 update (GB = MV1 result, pd = token table, gz = z-proj) --
#pragma unroll
        for (int rep = 0; rep < 2; rep++) {
            int u = l + 32 * rep;
            if (u < 50) {
                float b0[G], b1[G], b2[G], hold[G];
#pragma unroll
                for (int g = 0; g < G; g++) {
                    const float* gb = GB + g * 152;
                    b0[g] = gb[u]; b1[g] = gb[50 + u]; b2[g] = gb[100 + u];
                    hold[g] = H1[g * 52 + u];
                }
#pragma unroll
                for (int g = 0; g < G; g++) {
                    float a0 = pd[rep][0][g] + (rep ? gz1[0][g] : gz0[0][g]) + b0[g];
                    float a1 = pd[rep][1][g] + (rep ? gz1[1][g] : gz0[1][g]) + b1[g];
                    float a2 = pd[rep][2][g] + (rep ? gz1[2][g] : gz0[2][g]);
                    float r = sigmf(a0);
                    float z = sigmf(a1);
                    float n = tanhfast(a2 + r * b2[g]);
                    H1[g * 52 + u] = (1.0f - z) * n + z * hold[g];
                }
            }
        }
        __syncwarp();

        // -- MV2: gi2 = h1_new @ Wih2.T + bih2 --
        matvec_g<5>(W2, H1, B2, GB, l);
        __syncwarp();

        // -- gates2: h2 update from GB(gi2) + GA(gh2) --
#pragma unroll
        for (int rep = 0; rep < 2; rep++) {
            int u = l + 32 * rep;
            if (u < 50) {
                float i0[G], i1[G], i2v[G], h0[G], h1v[G], h2v[G], hold[G];
#pragma unroll
                for (int g = 0; g < G; g++) {
                    const float* gi = GB + g * 152;
                    const float* gh = GA + g * 152;
                    i0[g] = gi[u]; i1[g] = gi[50 + u]; i2v[g] = gi[100 + u];
                    h0[g] = gh[u]; h1v[g] = gh[50 + u]; h2v[g] = gh[100 + u];
                    hold[g] = H2[g * 52 + u];
                }
#pragma unroll
                for (int g = 0; g < G; g++) {
                    float r = sigmf(i0[g] + h0[g]);
                    float z = sigmf(i1[g] + h1v[g]);
                    float n = tanhfast(i2v[g] + r * h2v[g]);
                    H2[g * 52 + u] = (1.0f - z) * n + z * hold[g];
                }
            }
        }
        __syncwarp();

        // -- output projection: vals = WO @ h2 + oz --
        float vals[4][G];
        {
            unsigned long long aco[4][G];
#pragma unroll
            for (int i = 0; i < 4; i++)
#pragma unroll
                for (int g = 0; g < G; g++) aco[i][g] = packf2(oz[i][g], 0.0f);
#pragma unroll 1
            for (int j = 0; j < 13; j++) {
                ulonglong2 hq2[G];
#pragma unroll
                for (int g = 0; g < G; g++)
                    hq2[g] = *reinterpret_cast<const ulonglong2*>(H2 + g * 52 + j * 4);
#pragma unroll
                for (int i = 0; i < 4; i++) {
                    ulonglong2 wv = *reinterpret_cast<const ulonglong2*>(WO + (l + 32 * i) * 52 + j * 4);
#pragma unroll
                    for (int g = 0; g < G; g++) {
                        aco[i][g] = fma2(wv.x, hq2[g].x, aco[i][g]);
                        aco[i][g] = fma2(wv.y, hq2[g].y, aco[i][g]);
                    }
                }
            }
#pragma unroll
            for (int i = 0; i < 4; i++)
#pragma unroll
                for (int g = 0; g < G; g++) {
                    float2 f = u2f(aco[i][g]);
                    vals[i][g] = f.x + f.y;
                }
        }

        // -- MV1 for NEXT step (h1 final; GB free) — overlaps softmax latency --
        matvec_g<5>(W1, H1, B1, GB, l);
        __syncwarp();

        // -- merged argmax + direct exp-sum (|vals|<~3, no max-shift needed) --
        float m[G]; int mi[G]; float ss[G];
#pragma unroll
        for (int g = 0; g < G; g++) {
            m[g] = vals[0][g]; mi[g] = l;
            ss[g] = __expf(vals[0][g]);
#pragma unroll
            for (int i = 1; i < 4; i++) {
                ss[g] += __expf(vals[i][g]);
                if (vals[i][g] > m[g]) { m[g] = vals[i][g]; mi[g] = l + 32 * i; }
            }
        }
#pragma unroll
        for (int off = 16; off >= 1; off >>= 1) {
#pragma unroll
            for (int g = 0; g < G; g++) {
                float m2 = __shfl_xor_sync(0xffffffffu, m[g], off);
                int   i2 = __shfl_xor_sync(0xffffffffu, mi[g], off);
                float s2 = __shfl_xor_sync(0xffffffffu, ss[g], off);
                ss[g] += s2;
                if (m2 > m[g] || (m2 == m[g] && i2 < mi[g])) { m[g] = m2; mi[g] = i2; }
            }
        }
#pragma unroll
        for (int g = 0; g < G; g++) {
            float lse = __logf(ss[g]);
            ct[g] = mi[g];
            int b = bgrp + g;
            if (b < Bsz) {
                float* wp = out + (size_t)b * (MAXL * Cvoc) + (size_t)t * Cvoc;
#pragma unroll
                for (int i = 0; i < 4; i++) wp[l + 32 * i] = vals[i][g] - lse;
            }
        }
        __syncwarp();
    }
}

// ---------------------------------------------------------------------------
// Launch
// ---------------------------------------------------------------------------
extern "C" void kernel_launch(void* const* d_in, const int* in_sizes, int n_in,
                              void* d_out, int out_size) {
    const int*   x         = (const int*)  d_in[0];
    const float* embed_enc = (const float*)d_in[1];
    const float* Wih_f     = (const float*)d_in[2];
    const float* Whh_f     = (const float*)d_in[3];
    const float* bih_f     = (const float*)d_in[4];
    const float* bhh_f     = (const float*)d_in[5];
    const float* Wih_b     = (const float*)d_in[6];
    const float* Whh_b     = (const float*)d_in[7];  (void)Whh_b;  // h0=0: unused
    const float* bih_b     = (const float*)d_in[8];
    const float* bhh_b     = (const float*)d_in[9];
    const float* Wh2p      = (const float*)d_in[10];
    const float* bh2p      = (const float*)d_in[11];
    const float* embed_dec = (const float*)d_in[12];
    const float* Wz2h      = (const float*)d_in[13];
    const float* bz2h      = (const float*)d_in[14];
    const float* Wih1      = (const float*)d_in[15];
    const float* Whh1      = (const float*)d_in[16];
    const float* bih1      = (const float*)d_in[17];
    const float* bhh1      = (const float*)d_in[18];
    const float* Wih2      = (const float*)d_in[19];
    const float* Whh2      = (const float*)d_in[20];
    const float* bih2      = (const float*)d_in[21];
    const float* bhh2      = (const float*)d_in[22];
    const float* Wh2o      = (const float*)d_in[23];
    const float* bh2o      = (const float*)d_in[24];
    float* out = (float*)d_out;

    cudaFuncSetAttribute(vae_main, cudaFuncAttributeMaxDynamicSharedMemorySize, SMEM_BYTES);

    vae_pre<<<Cvoc, 160>>>(embed_enc, Wih_f, bih_f, Wih_b, bih_b, bhh_b, embed_dec, Wih1);
    vae_main<<<NBLK, TPB, SMEM_BYTES>>>(x,
                                        Whh_f, bhh_f, Wh2p, bh2p, Wz2h, bz2h,
                                        Wih1, bih1, Whh1, bhh1, Wih2, bih2,
                                        Whh2, bhh2, Wh2o, bh2o, out);
}

// round 14
// speedup vs baseline: 1.2149x; 1.0551x over previous
#include <cuda_runtime.h>
#include <cuda_bf16.h>
#include <cstdint>
#include <cstddef>

// ---------------------------------------------------------------------------
// Problem constants
// ---------------------------------------------------------------------------
#define Bsz    8192
#define Tlen   64
#define MAXL   64
#define Cvoc   128
#define NS     56                 // samples per block
#define TPB    448                // 14 warps; each warp owns 4 samples
#define NBLK   147                // one wave on 148 SMs
#define G      4                  // samples per warp

#define WORDS_ELEMS (Bsz * MAXL * Cvoc)
#define MU_OFF      ((size_t)WORDS_ELEMS)
#define LV_OFF      (MU_OFF + (size_t)Bsz * 20)

// ---------------------------------------------------------------------------
// Device scratch (static __device__ arrays: allocation-free)
// ---------------------------------------------------------------------------
__device__ float g_encf[Cvoc * 152];          // bih_f + embed_enc[c] @ Wih_f.T
__device__ float g_dect[Cvoc * 152];          // silu(embed_dec[c]) @ Wih1[:, :50].T
__device__ float g_bh  [Cvoc * 52];           // backward-cell output per token (h0=0)

// ---------------------------------------------------------------------------
// Shared memory layout (floats). Total 54944 floats = 219,776 B
// ---------------------------------------------------------------------------
#define oW1 0                    // 160x52
#define oW2 8320                 // 160x52   (token buffer overlay during encoder)
#define oW3 16640                // 160x52
#define oWO 24960                // 128x52
#define oB1 31616                // 160
#define oB2 31776                // 160
#define oB3 31936                // 160
#define oGA 32096                // 56x152
#define oGB 40608                // 56x152
#define oH1 49120                // 56x52
#define oH2 52032                // 56x52
#define SMEM_FLOATS 54944
#define SMEM_BYTES  (SMEM_FLOATS * 4)

// ---------------------------------------------------------------------------
// f32x2 packed FMA helpers
// ---------------------------------------------------------------------------
__device__ __forceinline__ unsigned long long fma2(unsigned long long a,
                                                   unsigned long long b,
                                                   unsigned long long c) {
    unsigned long long d;
    asm("fma.rn.f32x2 %0, %1, %2, %3;" : "=l"(d) : "l"(a), "l"(b), "l"(c));
    return d;
}
__device__ __forceinline__ float2 u2f(unsigned long long v) {
    float2 f;
    asm("mov.b64 {%0, %1}, %2;" : "=f"(f.x), "=f"(f.y) : "l"(v));
    return f;
}
__device__ __forceinline__ unsigned long long packf2(float x, float y) {
    unsigned long long v;
    asm("mov.b64 %0, {%1, %2};" : "=l"(v) : "f"(x), "f"(y));
    return v;
}
// precise (precompute-only)
__device__ __forceinline__ float sigm(float x) { return 1.0f / (1.0f + expf(-x)); }
// single-MUFU hot-loop nonlinearities (tanh.approx: abs err ~1e-5)
__device__ __forceinline__ float tanhapx(float x) {
    float y;
    asm("tanh.approx.f32 %0, %1;" : "=f"(y) : "f"(x));
    return y;
}
__device__ __forceinline__ float sigmt(float x) {
    return fmaf(tanhapx(0.5f * x), 0.5f, 0.5f);
}

// ---------------------------------------------------------------------------
// Warp-group matvec: rows l+32i (i<R, weights padded to >=32R x 52), G samples.
// ---------------------------------------------------------------------------
template<int R>
__device__ __forceinline__ void matvec_g(const float* __restrict__ W,
                                         const float* __restrict__ Hs,
                                         const float* __restrict__ Bv,
                                         float* __restrict__ Gout,
                                         int l) {
    unsigned long long acc[R][G];
#pragma unroll
    for (int i = 0; i < R; i++)
#pragma unroll
        for (int g = 0; g < G; g++) acc[i][g] = 0ull;
#pragma unroll 1
    for (int j = 0; j < 13; j++) {
        ulonglong2 hq[G];
#pragma unroll
        for (int g = 0; g < G; g++)
            hq[g] = *reinterpret_cast<const ulonglong2*>(Hs + g * 52 + j * 4);
#pragma unroll
        for (int i = 0; i < R; i++) {
            ulonglong2 wv = *reinterpret_cast<const ulonglong2*>(W + (l + 32 * i) * 52 + j * 4);
#pragma unroll
            for (int g = 0; g < G; g++) {
                acc[i][g] = fma2(wv.x, hq[g].x, acc[i][g]);
                acc[i][g] = fma2(wv.y, hq[g].y, acc[i][g]);
            }
        }
    }
#pragma unroll
    for (int i = 0; i < R; i++) {
        int row = l + 32 * i;
        if (row < 152) {
            float b = Bv[row];
#pragma unroll
            for (int g = 0; g < G; g++) {
                float2 f = u2f(acc[i][g]);
                Gout[g * 152 + row] = f.x + f.y + b;
            }
        }
    }
}

// ---------------------------------------------------------------------------
// Precompute kernel: per-token tables. Grid = 128 (one per token), 160 thr.
// Full precision (runs once; feeds everything).
// ---------------------------------------------------------------------------
__global__ void vae_pre(const float* __restrict__ embed_enc,
                        const float* __restrict__ Wih_f, const float* __restrict__ bih_f,
                        const float* __restrict__ Wih_b, const float* __restrict__ bih_b,
                        const float* __restrict__ bhh_b,
                        const float* __restrict__ embed_dec,
                        const float* __restrict__ Wih1) {
    __shared__ float ee[50];
    __shared__ float ed[50];
    int c = blockIdx.x;
    int t = threadIdx.x;
    if (t < 50) {
        ee[t] = embed_enc[c * 50 + t];
        float e = embed_dec[c * 50 + t];
        ed[t] = e / (1.0f + expf(-e));      // silu
    }
    __syncthreads();

    if (t < 152) {
        float a = 0.0f, d = 0.0f;
        if (t < 150) {
            a = bih_f[t];
            for (int j = 0; j < 50; j++) {
                a = fmaf(ee[j], Wih_f[t * 50 + j], a);
                d = fmaf(ed[j], Wih1[t * 70 + j], d);
            }
        }
        g_encf[c * 152 + t] = a;
        g_dect[c * 152 + t] = d;
    }
    if (t < 52) {
        float hv = 0.0f;
        if (t < 50) {
            float gr = bih_b[t], gz = bih_b[50 + t], gn = bih_b[100 + t];
            for (int j = 0; j < 50; j++) {
                float e = ee[j];
                gr = fmaf(e, Wih_b[t * 50 + j], gr);
                gz = fmaf(e, Wih_b[(50 + t) * 50 + j], gz);
                gn = fmaf(e, Wih_b[(100 + t) * 50 + j], gn);
            }
            float rr = sigm(gr + bhh_b[t]);
            float zz = sigm(gz + bhh_b[50 + t]);
            float nn = tanhf(gn + rr * bhh_b[100 + t]);
            hv = (1.0f - zz) * nn;          // h0 = 0 => h' = (1-z)*n
        }
        g_bh[c * 52 + t] = hv;
    }
}

// ---------------------------------------------------------------------------
// Main fused kernel
// ---------------------------------------------------------------------------
__global__ void __launch_bounds__(TPB, 1)
vae_main(const int* __restrict__ x,
         const float* __restrict__ Whh_f, const float* __restrict__ bhh_f,
         const float* __restrict__ Wh2p,  const float* __restrict__ bh2p,
         const float* __restrict__ Wz2h,  const float* __restrict__ bz2h,
         const float* __restrict__ Wih1,  const float* __restrict__ bih1,
         const float* __restrict__ Whh1,  const float* __restrict__ bhh1,
         const float* __restrict__ Wih2,  const float* __restrict__ bih2,
         const float* __restrict__ Whh2,  const float* __restrict__ bhh2,
         const float* __restrict__ Wh2o,  const float* __restrict__ bh2o,
         float* __restrict__ out) {
    extern __shared__ float sm[];
    const int tid  = threadIdx.x;
    const int wrp  = tid >> 5;          // 0..13
    const int l    = tid & 31;
    const int sb   = wrp * G;           // warp's sample base within block
    const int bgrp = blockIdx.x * NS + sb;

    float* W1 = sm + oW1;
    float* W2 = sm + oW2;
    float* W3 = sm + oW3;
    float* WO = sm + oWO;
    float* B1 = sm + oB1;
    float* B2 = sm + oB2;
    float* B3 = sm + oB3;
    float* GA = sm + oGA + sb * 152;
    float* GB = sm + oGB + sb * 152;
    float* H1 = sm + oH1 + sb * 52;
    float* H2 = sm + oH2 + sb * 52;
    int*   TOK = (int*)(sm + oW2);      // encoder-phase overlay of W2

    // ---- encoder weights (padded 160x52), tokens, zero H ----
    for (int i = tid; i < 160 * 52; i += TPB) {
        int row = i / 52, j = i % 52;
        W1[i] = (row < 150 && j < 50) ? Whh_f[row * 50 + j] : 0.0f;
    }
    for (int i = tid; i < 160; i += TPB) B1[i] = (i < 150) ? bhh_f[i] : 0.0f;
    for (int i = tid; i < NS * Tlen; i += TPB) {
        int s = i / Tlen;
        int b = blockIdx.x * NS + s; if (b >= Bsz) b = Bsz - 1;
        TOK[i] = x[b * Tlen + (i % Tlen)];
    }
    for (int i = tid; i < NS * 52; i += TPB) { sm[oH1 + i] = 0.0f; sm[oH2 + i] = 0.0f; }
    __syncthreads();

    // ================= ENCODER: 64 forward GRU steps =================
    for (int t = 0; t < Tlen; t++) {
        // prefetch token-table rows BEFORE matvec (hides L2 latency)
        float pv[2][3][G];
#pragma unroll
        for (int rep = 0; rep < 2; rep++) {
            int u = l + 32 * rep;
            if (u < 50) {
#pragma unroll
                for (int g = 0; g < G; g++) {
                    const float* T = g_encf + TOK[(sb + g) * Tlen + t] * 152;
                    pv[rep][0][g] = __ldg(T + u);
                    pv[rep][1][g] = __ldg(T + 50 + u);
                    pv[rep][2][g] = __ldg(T + 100 + u);
                }
            }
        }
        matvec_g<5>(W1, H1, B1, GB, l);
        __syncwarp();
#pragma unroll
        for (int rep = 0; rep < 2; rep++) {
            int u = l + 32 * rep;
            if (u < 50) {
                float b0[G], b1[G], b2[G], hold[G];
#pragma unroll
                for (int g = 0; g < G; g++) {
                    const float* gb = GB + g * 152;
                    b0[g] = gb[u]; b1[g] = gb[50 + u]; b2[g] = gb[100 + u];
                    hold[g] = H1[g * 52 + u];
                }
#pragma unroll
                for (int g = 0; g < G; g++) {
                    float r = sigmt(pv[rep][0][g] + b0[g]);
                    float z = sigmt(pv[rep][1][g] + b1[g]);
                    float n = tanhapx(pv[rep][2][g] + r * b2[g]);
                    H1[g * 52 + u] = fmaf(z, hold[g] - n, n);
                }
            }
        }
        __syncwarp();
    }

    // ---- backward cell add (pure table) ----
#pragma unroll
    for (int rep = 0; rep < 2; rep++) {
        int u = l + 32 * rep;
        if (u < 50) {
#pragma unroll
            for (int g = 0; g < G; g++) {
                int cl = TOK[(sb + g) * Tlen + Tlen - 1];
                H1[g * 52 + u] += __ldg(g_bh + cl * 52 + u);
            }
        }
    }
    __syncwarp();

    // ---- p = h_enc@Wh2p.T + bh2p ; z=mu -> GB[0:20]; mu/logvar out ----
#pragma unroll
    for (int k = 0; k < 2; k++) {
        int row = l + 32 * k;
        if (row < 40) {
            float accv[G];
#pragma unroll
            for (int g = 0; g < G; g++) accv[g] = __ldg(bh2p + row);
            for (int j = 0; j < 50; j++) {
                float wv = __ldg(Wh2p + row * 50 + j);
#pragma unroll
                for (int g = 0; g < G; g++) accv[g] = fmaf(wv, H1[g * 52 + j], accv[g]);
            }
            for (int g = 0; g < G; g++) {
                int b = bgrp + g;
                if (row < 20) {
                    GB[g * 152 + row] = accv[g];         // z = mu
                    if (b < Bsz) out[MU_OFF + (size_t)b * 20 + row] = accv[g];
                } else {
                    if (b < Bsz) out[LV_OFF + (size_t)b * 20 + (row - 20)] = accv[g];
                }
            }
        }
    }
    __syncwarp();

    // ---- h_init (h1=h2) from z ----
#pragma unroll
    for (int k = 0; k < 2; k++) {
        int row = l + 32 * k;
        if (row < 50) {
            float accv[G];
#pragma unroll
            for (int g = 0; g < G; g++) accv[g] = __ldg(bz2h + row);
            for (int j = 0; j < 20; j++) {
                float wv = __ldg(Wz2h + row * 20 + j);
#pragma unroll
                for (int g = 0; g < G; g++) accv[g] = fmaf(wv, GB[g * 152 + j], accv[g]);
            }
            for (int g = 0; g < G; g++) { H1[g * 52 + row] = accv[g]; H2[g * 52 + row] = accv[g]; }
        }
    }

    // ---- giz = bih1 + z @ Wih1[:,50:70].T  -> staged in GA (smem) ----
#pragma unroll
    for (int k = 0; k < 5; k++) {
        int row = l + 32 * k;
        if (row < 150) {
            float accv[G];
#pragma unroll
            for (int g = 0; g < G; g++) accv[g] = __ldg(bih1 + row);
            for (int j = 0; j < 20; j++) {
                float wv = __ldg(Wih1 + row * 70 + 50 + j);
#pragma unroll
                for (int g = 0; g < G; g++) accv[g] = fmaf(wv, GB[g * 152 + j], accv[g]);
            }
            for (int g = 0; g < G; g++) GA[g * 152 + row] = accv[g];
        }
    }

    // ---- outz = bh2o + z @ Wh2o[:,50:70].T -> HELD IN REGISTERS (oz) ----
    float oz[4][G];
#pragma unroll
    for (int k = 0; k < 4; k++) {
        int row = l + 32 * k;   // < 128 always
#pragma unroll
        for (int g = 0; g < G; g++) oz[k][g] = __ldg(bh2o + row);
        for (int j = 0; j < 20; j++) {
            float wv = __ldg(Wh2o + row * 70 + 50 + j);
#pragma unroll
            for (int g = 0; g < G; g++) oz[k][g] = fmaf(wv, GB[g * 152 + j], oz[k][g]);
        }
    }
    __syncwarp();

    // ---- pull this lane's 6 giz values per sample into registers ----
    float gz0[3][G], gz1[3][G];
#pragma unroll
    for (int g = 0; g < G; g++) {
        const float* gp = GA + g * 152;
        gz0[0][g] = gp[l];       gz0[1][g] = gp[50 + l];  gz0[2][g] = gp[100 + l];
        if (l < 18) {
            gz1[0][g] = gp[32 + l]; gz1[1][g] = gp[82 + l]; gz1[2][g] = gp[132 + l];
        } else {
            gz1[0][g] = 0.0f; gz1[1][g] = 0.0f; gz1[2][g] = 0.0f;
        }
    }
    __syncthreads();

    // ---- swap smem to decoder weights (W2 overwrites token buffer) ----
    for (int i = tid; i < 160 * 52; i += TPB) {
        int row = i / 52, j = i % 52;
        bool ok = (row < 150 && j < 50);
        W1[i] = ok ? Whh1[row * 50 + j] : 0.0f;
        W2[i] = ok ? Wih2[row * 50 + j] : 0.0f;
        W3[i] = ok ? Whh2[row * 50 + j] : 0.0f;
    }
    for (int i = tid; i < 128 * 52; i += TPB) {
        int row = i / 52, j = i % 52;
        WO[i] = (j < 50) ? Wh2o[row * 70 + j] : 0.0f;
    }
    for (int i = tid; i < 160; i += TPB) {
        bool ok = (i < 150);
        B1[i] = ok ? bhh1[i] : 0.0f;
        B2[i] = ok ? bih2[i] : 0.0f;
        B3[i] = ok ? bhh2[i] : 0.0f;
    }
    __syncthreads();

    // ================= DECODER: 64 autoregressive steps (software-pipelined) ==
    int ct[G];
#pragma unroll
    for (int g = 0; g < G; g++) ct[g] = 1;   // SOS

    // prologue: MV1 for step 0
    matvec_g<5>(W1, H1, B1, GB, l);
    __syncwarp();

    for (int t = 0; t < MAXL; t++) {
        // -- prefetch token-table rows for gates1 (covered by MV3) --
        float pd[2][3][G];
#pragma unroll
        for (int rep = 0; rep < 2; rep++) {
            int u = l + 32 * rep;
            if (u < 50) {
#pragma unroll
                for (int g = 0; g < G; g++) {
                    const float* T = g_dect + ct[g] * 152;
                    pd[rep][0][g] = __ldg(T + u);
                    pd[rep][1][g] = __ldg(T + 50 + u);
                    pd[rep][2][g] = __ldg(T + 100 + u);
                }
            }
        }

        // -- MV3: gh2 = h2 @ Whh2.T + bhh2  (independent of gates1) --
        matvec_g<5>(W3, H2, B3, GA, l);
        __syncwarp();

        // -- gates1: h1 update (GB = MV1 result, pd = token table, gz = z-proj) --
#pragma unroll
        for (int rep = 0; rep < 2; rep++) {
            int u = l + 32 * rep;
            if (u < 50) {
                float b0[G], b1[G], b2[G], hold[G];
#pragma unroll
                for (int g = 0; g < G; g++) {
                    const float* gb = GB + g * 152;
                    b0[g] = gb[u]; b1[g] = gb[50 + u]; b2[g] = gb[100 + u];
                    hold[g] = H1[g * 52 + u];
                }
#pragma unroll
                for (int g = 0; g < G; g++) {
                    float a0 = pd[rep][0][g] + (rep ? gz1[0][g] : gz0[0][g]) + b0[g];
                    float a1 = pd[rep][1][g] + (rep ? gz1[1][g] : gz0[1][g]) + b1[g];
                    float a2 = pd[rep][2][g] + (rep ? gz1[2][g] : gz0[2][g]);
                    float r = sigmt(a0);
                    float z = sigmt(a1);
                    float n = tanhapx(a2 + r * b2[g]);
                    H1[g * 52 + u] = fmaf(z, hold[g] - n, n);
                }
            }
        }
        __syncwarp();

        // -- MV2: gi2 = h1_new @ Wih2.T + bih2 --
        matvec_g<5>(W2, H1, B2, GB, l);
        __syncwarp();

        // -- gates2: h2 update from GB(gi2) + GA(gh2) --
#pragma unroll
        for (int rep = 0; rep < 2; rep++) {
            int u = l + 32 * rep;
            if (u < 50) {
                float i0[G], i1[G], i2v[G], h0[G], h1v[G], h2v[G], hold[G];
#pragma unroll
                for (int g = 0; g < G; g++) {
                    const float* gi = GB + g * 152;
                    const float* gh = GA + g * 152;
                    i0[g] = gi[u]; i1[g] = gi[50 + u]; i2v[g] = gi[100 + u];
                    h0[g] = gh[u]; h1v[g] = gh[50 + u]; h2v[g] = gh[100 + u];
                    hold[g] = H2[g * 52 + u];
                }
#pragma unroll
                for (int g = 0; g < G; g++) {
                    float r = sigmt(i0[g] + h0[g]);
                    float z = sigmt(i1[g] + h1v[g]);
                    float n = tanhapx(i2v[g] + r * h2v[g]);
                    H2[g * 52 + u] = fmaf(z, hold[g] - n, n);
                }
            }
        }
        __syncwarp();

        // -- output projection: vals = WO @ h2 + oz --
        float vals[4][G];
        {
            unsigned long long aco[4][G];
#pragma unroll
            for (int i = 0; i < 4; i++)
#pragma unroll
                for (int g = 0; g < G; g++) aco[i][g] = packf2(oz[i][g], 0.0f);
#pragma unroll 1
            for (int j = 0; j < 13; j++) {
                ulonglong2 hq2[G];
#pragma unroll
                for (int g = 0; g < G; g++)
                    hq2[g] = *reinterpret_cast<const ulonglong2*>(H2 + g * 52 + j * 4);
#pragma unroll
                for (int i = 0; i < 4; i++) {
                    ulonglong2 wv = *reinterpret_cast<const ulonglong2*>(WO + (l + 32 * i) * 52 + j * 4);
#pragma unroll
                    for (int g = 0; g < G; g++) {
                        aco[i][g] = fma2(wv.x, hq2[g].x, aco[i][g]);
                        aco[i][g] = fma2(wv.y, hq2[g].y, aco[i][g]);
                    }
                }
            }
#pragma unroll
            for (int i = 0; i < 4; i++)
#pragma unroll
                for (int g = 0; g < G; g++) {
                    float2 f = u2f(aco[i][g]);
                    vals[i][g] = f.x + f.y;
                }
        }

        // -- MV1 for NEXT step (h1 final; GB free) — overlaps softmax latency --
        matvec_g<5>(W1, H1, B1, GB, l);
        __syncwarp();

        // -- merged argmax + direct exp-sum (|vals|<~3, no max-shift needed) --
        float m[G]; int mi[G]; float ss[G];
#pragma unroll
        for (int g = 0; g < G; g++) {
            m[g] = vals[0][g]; mi[g] = l;
            ss[g] = __expf(vals[0][g]);
#pragma unroll
            for (int i = 1; i < 4; i++) {
                ss[g] += __expf(vals[i][g]);
                if (vals[i][g] > m[g]) { m[g] = vals[i][g]; mi[g] = l + 32 * i; }
            }
        }
#pragma unroll
        for (int off = 16; off >= 1; off >>= 1) {
#pragma unroll
            for (int g = 0; g < G; g++) {
                float m2 = __shfl_xor_sync(0xffffffffu, m[g], off);
                int   i2 = __shfl_xor_sync(0xffffffffu, mi[g], off);
                float s2 = __shfl_xor_sync(0xffffffffu, ss[g], off);
                ss[g] += s2;
                if (m2 > m[g] || (m2 == m[g] && i2 < mi[g])) { m[g] = m2; mi[g] = i2; }
            }
        }
#pragma unroll
        for (int g = 0; g < G; g++) {
            float lse = __logf(ss[g]);
            ct[g] = mi[g];
            int b = bgrp + g;
            if (b < Bsz) {
                float* wp = out + (size_t)b * (MAXL * Cvoc) + (size_t)t * Cvoc;
#pragma unroll
                for (int i = 0; i < 4; i++) wp[l + 32 * i] = vals[i][g] - lse;
            }
        }
        __syncwarp();
    }
}

// ---------------------------------------------------------------------------
// Launch
// ---------------------------------------------------------------------------
extern "C" void kernel_launch(void* const* d_in, const int* in_sizes, int n_in,
                              void* d_out, int out_size) {
    const int*   x         = (const int*)  d_in[0];
    const float* embed_enc = (const float*)d_in[1];
    const float* Wih_f     = (const float*)d_in[2];
    const float* Whh_f     = (const float*)d_in[3];
    const float* bih_f     = (const float*)d_in[4];
    const float* bhh_f     = (const float*)d_in[5];
    const float* Wih_b     = (const float*)d_in[6];
    const float* Whh_b     = (const float*)d_in[7];  (void)Whh_b;  // h0=0: unused
    const float* bih_b     = (const float*)d_in[8];
    const float* bhh_b     = (const float*)d_in[9];
    const float* Wh2p      = (const float*)d_in[10];
    const float* bh2p      = (const float*)d_in[11];
    const float* embed_dec = (const float*)d_in[12];
    const float* Wz2h      = (const float*)d_in[13];
    const float* bz2h      = (const float*)d_in[14];
    const float* Wih1      = (const float*)d_in[15];
    const float* Whh1      = (const float*)d_in[16];
    const float* bih1      = (const float*)d_in[17];
    const float* bhh1      = (const float*)d_in[18];
    const float* Wih2      = (const float*)d_in[19];
    const float* Whh2      = (const float*)d_in[20];
    const float* bih2      = (const float*)d_in[21];
    const float* bhh2      = (const float*)d_in[22];
    const float* Wh2o      = (const float*)d_in[23];
    const float* bh2o      = (const float*)d_in[24];
    float* out = (float*)d_out;

    cudaFuncSetAttribute(vae_main, cudaFuncAttributeMaxDynamicSharedMemorySize, SMEM_BYTES);

    vae_pre<<<Cvoc, 160>>>(embed_enc, Wih_f, bih_f, Wih_b, bih_b, bhh_b, embed_dec, Wih1);
    vae_main<<<NBLK, TPB, SMEM_BYTES>>>(x,
                                        Whh_f, bhh_f, Wh2p, bh2p, Wz2h, bz2h,
                                        Wih1, bih1, Whh1, bhh1, Wih2, bih2,
                                        Whh2, bhh2, Wh2o, bh2o, out);
}

// round 15
// speedup vs baseline: 1.2212x; 1.0052x over previous
#include <cuda_runtime.h>
#include <cuda_bf16.h>
#include <cstdint>
#include <cstddef>

// ---------------------------------------------------------------------------
// Problem constants
// ---------------------------------------------------------------------------
#define Bsz    8192
#define Tlen   64
#define MAXL   64
#define Cvoc   128
#define NS     56                 // samples per block
#define TPB    448                // 14 warps; each warp owns 4 samples
#define NBLK   147                // one wave on 148 SMs
#define G      4                  // samples per warp

#define WORDS_ELEMS (Bsz * MAXL * Cvoc)
#define MU_OFF      ((size_t)WORDS_ELEMS)
#define LV_OFF      (MU_OFF + (size_t)Bsz * 20)

// ---------------------------------------------------------------------------
// Device scratch (static __device__ arrays: allocation-free)
// ---------------------------------------------------------------------------
__device__ float g_encf[Cvoc * 152];          // bih_f + embed_enc[c] @ Wih_f.T
__device__ float g_dect[Cvoc * 152];          // silu(embed_dec[c]) @ Wih1[:, :50].T
__device__ float g_bh  [Cvoc * 52];           // backward-cell output per token (h0=0)

// ---------------------------------------------------------------------------
// Shared memory layout (floats). Total 54944 floats = 219,776 B
// ---------------------------------------------------------------------------
#define oW1 0                    // 160x52
#define oW2 8320                 // 160x52   (token buffer overlay during encoder)
#define oW3 16640                // 160x52
#define oWO 24960                // 128x52
#define oB1 31616                // 160
#define oB2 31776                // 160
#define oB3 31936                // 160
#define oGA 32096                // 56x152
#define oGB 40608                // 56x152
#define oH1 49120                // 56x52
#define oH2 52032                // 56x52
#define SMEM_FLOATS 54944
#define SMEM_BYTES  (SMEM_FLOATS * 4)

// ---------------------------------------------------------------------------
// f32x2 packed FMA helpers
// ---------------------------------------------------------------------------
__device__ __forceinline__ unsigned long long fma2(unsigned long long a,
                                                   unsigned long long b,
                                                   unsigned long long c) {
    unsigned long long d;
    asm("fma.rn.f32x2 %0, %1, %2, %3;" : "=l"(d) : "l"(a), "l"(b), "l"(c));
    return d;
}
__device__ __forceinline__ float2 u2f(unsigned long long v) {
    float2 f;
    asm("mov.b64 {%0, %1}, %2;" : "=f"(f.x), "=f"(f.y) : "l"(v));
    return f;
}
__device__ __forceinline__ unsigned long long packf2(float x, float y) {
    unsigned long long v;
    asm("mov.b64 %0, {%1, %2};" : "=l"(v) : "f"(x), "f"(y));
    return v;
}
// precise (precompute-only)
__device__ __forceinline__ float sigm(float x) { return 1.0f / (1.0f + expf(-x)); }
// single-MUFU hot-loop nonlinearities (tanh.approx: validated R14, no flips)
__device__ __forceinline__ float tanhapx(float x) {
    float y;
    asm("tanh.approx.f32 %0, %1;" : "=f"(y) : "f"(x));
    return y;
}
__device__ __forceinline__ float sigmt(float x) {
    return fmaf(tanhapx(0.5f * x), 0.5f, 0.5f);
}
// monotonic float->uint key for integer max-reduction
__device__ __forceinline__ unsigned fkey(float f) {
    unsigned u = __float_as_uint(f);
    return (u & 0x80000000u) ? ~u : (u | 0x80000000u);
}
__device__ __forceinline__ unsigned redux_max_u32(unsigned v) {
    unsigned r;
    asm("redux.sync.max.u32 %0, %1, 0xffffffff;" : "=r"(r) : "r"(v));
    return r;
}
__device__ __forceinline__ int redux_min_s32(int v) {
    int r;
    asm("redux.sync.min.s32 %0, %1, 0xffffffff;" : "=r"(r) : "r"(v));
    return r;
}

// ---------------------------------------------------------------------------
// Warp-group matvec: rows l+32i (i<R, weights padded to >=32R x 52), G samples.
// ---------------------------------------------------------------------------
template<int R>
__device__ __forceinline__ void matvec_g(const float* __restrict__ W,
                                         const float* __restrict__ Hs,
                                         const float* __restrict__ Bv,
                                         float* __restrict__ Gout,
                                         int l) {
    unsigned long long acc[R][G];
#pragma unroll
    for (int i = 0; i < R; i++)
#pragma unroll
        for (int g = 0; g < G; g++) acc[i][g] = 0ull;
#pragma unroll 1
    for (int j = 0; j < 13; j++) {
        ulonglong2 hq[G];
#pragma unroll
        for (int g = 0; g < G; g++)
            hq[g] = *reinterpret_cast<const ulonglong2*>(Hs + g * 52 + j * 4);
#pragma unroll
        for (int i = 0; i < R; i++) {
            ulonglong2 wv = *reinterpret_cast<const ulonglong2*>(W + (l + 32 * i) * 52 + j * 4);
#pragma unroll
            for (int g = 0; g < G; g++) {
                acc[i][g] = fma2(wv.x, hq[g].x, acc[i][g]);
                acc[i][g] = fma2(wv.y, hq[g].y, acc[i][g]);
            }
        }
    }
#pragma unroll
    for (int i = 0; i < R; i++) {
        int row = l + 32 * i;
        if (row < 152) {
            float b = Bv[row];
#pragma unroll
            for (int g = 0; g < G; g++) {
                float2 f = u2f(acc[i][g]);
                Gout[g * 152 + row] = f.x + f.y + b;
            }
        }
    }
}

// ---------------------------------------------------------------------------
// Precompute kernel: per-token tables. Grid = 128 (one per token), 160 thr.
// Full precision (runs once; feeds everything).
// ---------------------------------------------------------------------------
__global__ void vae_pre(const float* __restrict__ embed_enc,
                        const float* __restrict__ Wih_f, const float* __restrict__ bih_f,
                        const float* __restrict__ Wih_b, const float* __restrict__ bih_b,
                        const float* __restrict__ bhh_b,
                        const float* __restrict__ embed_dec,
                        const float* __restrict__ Wih1) {
    __shared__ float ee[50];
    __shared__ float ed[50];
    int c = blockIdx.x;
    int t = threadIdx.x;
    if (t < 50) {
        ee[t] = embed_enc[c * 50 + t];
        float e = embed_dec[c * 50 + t];
        ed[t] = e / (1.0f + expf(-e));      // silu
    }
    __syncthreads();

    if (t < 152) {
        float a = 0.0f, d = 0.0f;
        if (t < 150) {
            a = bih_f[t];
            for (int j = 0; j < 50; j++) {
                a = fmaf(ee[j], Wih_f[t * 50 + j], a);
                d = fmaf(ed[j], Wih1[t * 70 + j], d);
            }
        }
        g_encf[c * 152 + t] = a;
        g_dect[c * 152 + t] = d;
    }
    if (t < 52) {
        float hv = 0.0f;
        if (t < 50) {
            float gr = bih_b[t], gz = bih_b[50 + t], gn = bih_b[100 + t];
            for (int j = 0; j < 50; j++) {
                float e = ee[j];
                gr = fmaf(e, Wih_b[t * 50 + j], gr);
                gz = fmaf(e, Wih_b[(50 + t) * 50 + j], gz);
                gn = fmaf(e, Wih_b[(100 + t) * 50 + j], gn);
            }
            float rr = sigm(gr + bhh_b[t]);
            float zz = sigm(gz + bhh_b[50 + t]);
            float nn = tanhf(gn + rr * bhh_b[100 + t]);
            hv = (1.0f - zz) * nn;          // h0 = 0 => h' = (1-z)*n
        }
        g_bh[c * 52 + t] = hv;
    }
}

// ---------------------------------------------------------------------------
// Main fused kernel
// ---------------------------------------------------------------------------
__global__ void __launch_bounds__(TPB, 1)
vae_main(const int* __restrict__ x,
         const float* __restrict__ Whh_f, const float* __restrict__ bhh_f,
         const float* __restrict__ Wh2p,  const float* __restrict__ bh2p,
         const float* __restrict__ Wz2h,  const float* __restrict__ bz2h,
         const float* __restrict__ Wih1,  const float* __restrict__ bih1,
         const float* __restrict__ Whh1,  const float* __restrict__ bhh1,
         const float* __restrict__ Wih2,  const float* __restrict__ bih2,
         const float* __restrict__ Whh2,  const float* __restrict__ bhh2,
         const float* __restrict__ Wh2o,  const float* __restrict__ bh2o,
         float* __restrict__ out) {
    extern __shared__ float sm[];
    const int tid  = threadIdx.x;
    const int wrp  = tid >> 5;          // 0..13
    const int l    = tid & 31;
    const int sb   = wrp * G;           // warp's sample base within block
    const int bgrp = blockIdx.x * NS + sb;

    float* W1 = sm + oW1;
    float* W2 = sm + oW2;
    float* W3 = sm + oW3;
    float* WO = sm + oWO;
    float* B1 = sm + oB1;
    float* B2 = sm + oB2;
    float* B3 = sm + oB3;
    float* GA = sm + oGA + sb * 152;
    float* GB = sm + oGB + sb * 152;
    float* H1 = sm + oH1 + sb * 52;
    float* H2 = sm + oH2 + sb * 52;
    int*   TOK = (int*)(sm + oW2);      // encoder-phase overlay of W2

    // ---- encoder weights (padded 160x52), tokens, zero H ----
    for (int i = tid; i < 160 * 52; i += TPB) {
        int row = i / 52, j = i % 52;
        W1[i] = (row < 150 && j < 50) ? Whh_f[row * 50 + j] : 0.0f;
    }
    for (int i = tid; i < 160; i += TPB) B1[i] = (i < 150) ? bhh_f[i] : 0.0f;
    for (int i = tid; i < NS * Tlen; i += TPB) {
        int s = i / Tlen;
        int b = blockIdx.x * NS + s; if (b >= Bsz) b = Bsz - 1;
        TOK[i] = x[b * Tlen + (i % Tlen)];
    }
    for (int i = tid; i < NS * 52; i += TPB) { sm[oH1 + i] = 0.0f; sm[oH2 + i] = 0.0f; }
    __syncthreads();

    // ================= ENCODER: 64 forward GRU steps =================
    for (int t = 0; t < Tlen; t++) {
        // prefetch token-table rows BEFORE matvec (hides L2 latency)
        float pv[2][3][G];
#pragma unroll
        for (int rep = 0; rep < 2; rep++) {
            int u = l + 32 * rep;
            if (u < 50) {
#pragma unroll
                for (int g = 0; g < G; g++) {
                    const float* T = g_encf + TOK[(sb + g) * Tlen + t] * 152;
                    pv[rep][0][g] = __ldg(T + u);
                    pv[rep][1][g] = __ldg(T + 50 + u);
                    pv[rep][2][g] = __ldg(T + 100 + u);
                }
            }
        }
        matvec_g<5>(W1, H1, B1, GB, l);
        __syncwarp();
#pragma unroll
        for (int rep = 0; rep < 2; rep++) {
            int u = l + 32 * rep;
            if (u < 50) {
                float b0[G], b1[G], b2[G], hold[G];
#pragma unroll
                for (int g = 0; g < G; g++) {
                    const float* gb = GB + g * 152;
                    b0[g] = gb[u]; b1[g] = gb[50 + u]; b2[g] = gb[100 + u];
                    hold[g] = H1[g * 52 + u];
                }
#pragma unroll
                for (int g = 0; g < G; g++) {
                    float r = sigmt(pv[rep][0][g] + b0[g]);
                    float z = sigmt(pv[rep][1][g] + b1[g]);
                    float n = tanhapx(pv[rep][2][g] + r * b2[g]);
                    H1[g * 52 + u] = fmaf(z, hold[g] - n, n);
                }
            }
        }
        __syncwarp();
    }

    // ---- backward cell add (pure table) ----
#pragma unroll
    for (int rep = 0; rep < 2; rep++) {
        int u = l + 32 * rep;
        if (u < 50) {
#pragma unroll
            for (int g = 0; g < G; g++) {
                int cl = TOK[(sb + g) * Tlen + Tlen - 1];
                H1[g * 52 + u] += __ldg(g_bh + cl * 52 + u);
            }
        }
    }
    __syncwarp();

    // ---- p = h_enc@Wh2p.T + bh2p ; z=mu -> GB[0:20]; mu/logvar out ----
#pragma unroll
    for (int k = 0; k < 2; k++) {
        int row = l + 32 * k;
        if (row < 40) {
            float accv[G];
#pragma unroll
            for (int g = 0; g < G; g++) accv[g] = __ldg(bh2p + row);
            for (int j = 0; j < 50; j++) {
                float wv = __ldg(Wh2p + row * 50 + j);
#pragma unroll
                for (int g = 0; g < G; g++) accv[g] = fmaf(wv, H1[g * 52 + j], accv[g]);
            }
            for (int g = 0; g < G; g++) {
                int b = bgrp + g;
                if (row < 20) {
                    GB[g * 152 + row] = accv[g];         // z = mu
                    if (b < Bsz) out[MU_OFF + (size_t)b * 20 + row] = accv[g];
                } else {
                    if (b < Bsz) out[LV_OFF + (size_t)b * 20 + (row - 20)] = accv[g];
                }
            }
        }
    }
    __syncwarp();

    // ---- h_init (h1=h2) from z ----
#pragma unroll
    for (int k = 0; k < 2; k++) {
        int row = l + 32 * k;
        if (row < 50) {
            float accv[G];
#pragma unroll
            for (int g = 0; g < G; g++) accv[g] = __ldg(bz2h + row);
            for (int j = 0; j < 20; j++) {
                float wv = __ldg(Wz2h + row * 20 + j);
#pragma unroll
                for (int g = 0; g < G; g++) accv[g] = fmaf(wv, GB[g * 152 + j], accv[g]);
            }
            for (int g = 0; g < G; g++) { H1[g * 52 + row] = accv[g]; H2[g * 52 + row] = accv[g]; }
        }
    }

    // ---- giz = bih1 + z @ Wih1[:,50:70].T  -> staged in GA (smem) ----
#pragma unroll
    for (int k = 0; k < 5; k++) {
        int row = l + 32 * k;
        if (row < 150) {
            float accv[G];
#pragma unroll
            for (int g = 0; g < G; g++) accv[g] = __ldg(bih1 + row);
            for (int j = 0; j < 20; j++) {
                float wv = __ldg(Wih1 + row * 70 + 50 + j);
#pragma unroll
                for (int g = 0; g < G; g++) accv[g] = fmaf(wv, GB[g * 152 + j], accv[g]);
            }
            for (int g = 0; g < G; g++) GA[g * 152 + row] = accv[g];
        }
    }

    // ---- outz = bh2o + z @ Wh2o[:,50:70].T -> HELD IN REGISTERS (oz) ----
    float oz[4][G];
#pragma unroll
    for (int k = 0; k < 4; k++) {
        int row = l + 32 * k;   // < 128 always
#pragma unroll
        for (int g = 0; g < G; g++) oz[k][g] = __ldg(bh2o + row);
        for (int j = 0; j < 20; j++) {
            float wv = __ldg(Wh2o + row * 70 + 50 + j);
#pragma unroll
            for (int g = 0; g < G; g++) oz[k][g] = fmaf(wv, GB[g * 152 + j], oz[k][g]);
        }
    }
    __syncwarp();

    // ---- pull this lane's 6 giz values per sample into registers ----
    float gz0[3][G], gz1[3][G];
#pragma unroll
    for (int g = 0; g < G; g++) {
        const float* gp = GA + g * 152;
        gz0[0][g] = gp[l];       gz0[1][g] = gp[50 + l];  gz0[2][g] = gp[100 + l];
        if (l < 18) {
            gz1[0][g] = gp[32 + l]; gz1[1][g] = gp[82 + l]; gz1[2][g] = gp[132 + l];
        } else {
            gz1[0][g] = 0.0f; gz1[1][g] = 0.0f; gz1[2][g] = 0.0f;
        }
    }
    __syncthreads();

    // ---- swap smem to decoder weights (W2 overwrites token buffer) ----
    for (int i = tid; i < 160 * 52; i += TPB) {
        int row = i / 52, j = i % 52;
        bool ok = (row < 150 && j < 50);
        W1[i] = ok ? Whh1[row * 50 + j] : 0.0f;
        W2[i] = ok ? Wih2[row * 50 + j] : 0.0f;
        W3[i] = ok ? Whh2[row * 50 + j] : 0.0f;
    }
    for (int i = tid; i < 128 * 52; i += TPB) {
        int row = i / 52, j = i % 52;
        WO[i] = (j < 50) ? Wh2o[row * 70 + j] : 0.0f;
    }
    for (int i = tid; i < 160; i += TPB) {
        bool ok = (i < 150);
        B1[i] = ok ? bhh1[i] : 0.0f;
        B2[i] = ok ? bih2[i] : 0.0f;
        B3[i] = ok ? bhh2[i] : 0.0f;
    }
    __syncthreads();

    // ================= DECODER: 64 autoregressive steps (software-pipelined) ==
    int ct[G];
#pragma unroll
    for (int g = 0; g < G; g++) ct[g] = 1;   // SOS

    // prologue: MV1 for step 0
    matvec_g<5>(W1, H1, B1, GB, l);
    __syncwarp();

    for (int t = 0; t < MAXL; t++) {
        // -- prefetch token-table rows for gates1 (covered by MV3) --
        float pd[2][3][G];
#pragma unroll
        for (int rep = 0; rep < 2; rep++) {
            int u = l + 32 * rep;
            if (u < 50) {
#pragma unroll
                for (int g = 0; g < G; g++) {
                    const float* T = g_dect + ct[g] * 152;
                    pd[rep][0][g] = __ldg(T + u);
                    pd[rep][1][g] = __ldg(T + 50 + u);
                    pd[rep][2][g] = __ldg(T + 100 + u);
                }
            }
        }

        // -- MV3: gh2 = h2 @ Whh2.T + bhh2 (writes GA; no hazard w/ gates1) --
        matvec_g<5>(W3, H2, B3, GA, l);
        // NO syncwarp here: gates1 reads GB (fenced at loop end) + pd + gz and
        // writes H1; MV3 reads H2/W3 and writes GA (read only by gates2, which
        // is fenced by the post-gates1 syncwarp). Lets gates1 overlap MV3 stalls.

        // -- gates1: h1 update (GB = MV1 result, pd = token table, gz = z-proj) --
#pragma unroll
        for (int rep = 0; rep < 2; rep++) {
            int u = l + 32 * rep;
            if (u < 50) {
                float b0[G], b1[G], b2[G], hold[G];
#pragma unroll
                for (int g = 0; g < G; g++) {
                    const float* gb = GB + g * 152;
                    b0[g] = gb[u]; b1[g] = gb[50 + u]; b2[g] = gb[100 + u];
                    hold[g] = H1[g * 52 + u];
                }
#pragma unroll
                for (int g = 0; g < G; g++) {
                    float a0 = pd[rep][0][g] + (rep ? gz1[0][g] : gz0[0][g]) + b0[g];
                    float a1 = pd[rep][1][g] + (rep ? gz1[1][g] : gz0[1][g]) + b1[g];
                    float a2 = pd[rep][2][g] + (rep ? gz1[2][g] : gz0[2][g]);
                    float r = sigmt(a0);
                    float z = sigmt(a1);
                    float n = tanhapx(a2 + r * b2[g]);
                    H1[g * 52 + u] = fmaf(z, hold[g] - n, n);
                }
            }
        }
        __syncwarp();   // orders H1 (for MV2) AND GA (for gates2)

        // -- MV2: gi2 = h1_new @ Wih2.T + bih2 --
        matvec_g<5>(W2, H1, B2, GB, l);
        __syncwarp();

        // -- gates2: h2 update from GB(gi2) + GA(gh2) --
#pragma unroll
        for (int rep = 0; rep < 2; rep++) {
            int u = l + 32 * rep;
            if (u < 50) {
                float i0[G], i1[G], i2v[G], h0[G], h1v[G], h2v[G], hold[G];
#pragma unroll
                for (int g = 0; g < G; g++) {
                    const float* gi = GB + g * 152;
                    const float* gh = GA + g * 152;
                    i0[g] = gi[u]; i1[g] = gi[50 + u]; i2v[g] = gi[100 + u];
                    h0[g] = gh[u]; h1v[g] = gh[50 + u]; h2v[g] = gh[100 + u];
                    hold[g] = H2[g * 52 + u];
                }
#pragma unroll
                for (int g = 0; g < G; g++) {
                    float r = sigmt(i0[g] + h0[g]);
                    float z = sigmt(i1[g] + h1v[g]);
                    float n = tanhapx(i2v[g] + r * h2v[g]);
                    H2[g * 52 + u] = fmaf(z, hold[g] - n, n);
                }
            }
        }
        __syncwarp();

        // -- output projection: vals = WO @ h2 + oz --
        float vals[4][G];
        {
            unsigned long long aco[4][G];
#pragma unroll
            for (int i = 0; i < 4; i++)
#pragma unroll
                for (int g = 0; g < G; g++) aco[i][g] = packf2(oz[i][g], 0.0f);
#pragma unroll 1
            for (int j = 0; j < 13; j++) {
                ulonglong2 hq2[G];
#pragma unroll
                for (int g = 0; g < G; g++)
                    hq2[g] = *reinterpret_cast<const ulonglong2*>(H2 + g * 52 + j * 4);
#pragma unroll
                for (int i = 0; i < 4; i++) {
                    ulonglong2 wv = *reinterpret_cast<const ulonglong2*>(WO + (l + 32 * i) * 52 + j * 4);
#pragma unroll
                    for (int g = 0; g < G; g++) {
                        aco[i][g] = fma2(wv.x, hq2[g].x, aco[i][g]);
                        aco[i][g] = fma2(wv.y, hq2[g].y, aco[i][g]);
                    }
                }
            }
#pragma unroll
            for (int i = 0; i < 4; i++)
#pragma unroll
                for (int g = 0; g < G; g++) {
                    float2 f = u2f(aco[i][g]);
                    vals[i][g] = f.x + f.y;
                }
        }

        // -- MV1 for NEXT step (h1 final; GB free) — overlaps softmax latency --
        matvec_g<5>(W1, H1, B1, GB, l);
        __syncwarp();

        // -- argmax via redux.sync + direct exp-sum butterfly --
#pragma unroll
        for (int g = 0; g < G; g++) {
            // within-lane max (strict >, keeps smallest row on tie)
            float m = vals[0][g]; int mi = l;
            float ss = __expf(vals[0][g]);
#pragma unroll
            for (int i = 1; i < 4; i++) {
                ss += __expf(vals[i][g]);
                if (vals[i][g] > m) { m = vals[i][g]; mi = l + 32 * i; }
            }
            // cross-lane argmax: ordered-int max, then min row index among ties
            unsigned gm = redux_max_u32(fkey(m));
            int cand = (fkey(m) == gm) ? mi : 0x7fffffff;
            ct[g] = redux_min_s32(cand);
            // cross-lane exp-sum
#pragma unroll
            for (int off = 16; off >= 1; off >>= 1)
                ss += __shfl_xor_sync(0xffffffffu, ss, off);
            float lse = __logf(ss);
            int b = bgrp + g;
            if (b < Bsz) {
                float* wp = out + (size_t)b * (MAXL * Cvoc) + (size_t)t * Cvoc;
#pragma unroll
                for (int i = 0; i < 4; i++) wp[l + 32 * i] = vals[i][g] - lse;
            }
        }
        __syncwarp();
    }
}

// ---------------------------------------------------------------------------
// Launch
// ---------------------------------------------------------------------------
extern "C" void kernel_launch(void* const* d_in, const int* in_sizes, int n_in,
                              void* d_out, int out_size) {
    const int*   x         = (const int*)  d_in[0];
    const float* embed_enc = (const float*)d_in[1];
    const float* Wih_f     = (const float*)d_in[2];
    const float* Whh_f     = (const float*)d_in[3];
    const float* bih_f     = (const float*)d_in[4];
    const float* bhh_f     = (const float*)d_in[5];
    const float* Wih_b     = (const float*)d_in[6];
    const float* Whh_b     = (const float*)d_in[7];  (void)Whh_b;  // h0=0: unused
    const float* bih_b     = (const float*)d_in[8];
    const float* bhh_b     = (const float*)d_in[9];
    const float* Wh2p      = (const float*)d_in[10];
    const float* bh2p      = (const float*)d_in[11];
    const float* embed_dec = (const float*)d_in[12];
    const float* Wz2h      = (const float*)d_in[13];
    const float* bz2h      = (const float*)d_in[14];
    const float* Wih1      = (const float*)d_in[15];
    const float* Whh1      = (const float*)d_in[16];
    const float* bih1      = (const float*)d_in[17];
    const float* bhh1      = (const float*)d_in[18];
    const float* Wih2      = (const float*)d_in[19];
    const float* Whh2      = (const float*)d_in[20];
    const float* bih2      = (const float*)d_in[21];
    const float* bhh2      = (const float*)d_in[22];
    const float* Wh2o      = (const float*)d_in[23];
    const float* bh2o      = (const float*)d_in[24];
    float* out = (float*)d_out;

    cudaFuncSetAttribute(vae_main, cudaFuncAttributeMaxDynamicSharedMemorySize, SMEM_BYTES);

    vae_pre<<<Cvoc, 160>>>(embed_enc, Wih_f, bih_f, Wih_b, bih_b, bhh_b, embed_dec, Wih1);
    vae_main<<<NBLK, TPB, SMEM_BYTES>>>(x,
                                        Whh_f, bhh_f, Wh2p, bh2p, Wz2h, bz2h,
                                        Wih1, bih1, Whh1, bhh1, Wih2, bih2,
                                        Whh2, bhh2, Wh2o, bh2o, out);
}